// round 14
// baseline (speedup 1.0000x reference)
#include <cuda_runtime.h>
#include <math.h>
#include <stdint.h>

#define BN 8
#define C 256
#define HWn 4096
#define KFULL 2304

// ---------------- scratch (device globals: allocation-free) ----------------
__device__ float g_xt [(size_t)BN*HWn*C];        // x NHWC, tf32-rounded
__device__ float g_y1h[(size_t)BN*HWn*C];        // conv1 NHWC raw -> (in place) bn+relu rounded
__device__ float g_d2 [(size_t)BN*C*HWn];        // deform conv raw NCHW
__device__ float g_res[(size_t)BN*C*HWn];        // 1x1 raw NCHW
__device__ float g_off[BN*18*HWn];
__device__ float g_mask[BN*9*HWn];
__device__ float g_col[(size_t)BN*HWn*KFULL];    // [b][pix][k=p*256+ci], rounded
__device__ float g_stats[6*256];
__device__ float g_ps[3*256*256];                // [cta][c]
__device__ float g_pq[3*256*256];
__device__ float g_w1p[256*KFULL];
__device__ float g_wdp[256*KFULL];
__device__ float g_wop[32*KFULL];
__device__ float g_wds[256*256];
__device__ float g_bp[32];

// ---------------- helpers -----------------------------------------------------
__device__ __forceinline__ unsigned f2tf(float v) {
    unsigned u; asm("cvt.rna.tf32.f32 %0, %1;" : "=r"(u) : "f"(v)); return u;
}
__device__ __forceinline__ float f2tff(float v) { return __uint_as_float(f2tf(v)); }
__device__ __forceinline__ uint32_t s2u(const void* p) {
    uint32_t a;
    asm("{ .reg .u64 t; cvta.to.shared.u64 t, %1; cvt.u32.u64 %0, t; }" : "=r"(a) : "l"(p));
    return a;
}
__device__ __forceinline__ void cpa16(uint32_t dst, const void* src, bool v) {
    int sz = v ? 16 : 0;
    asm volatile("cp.async.cg.shared.global [%0], [%1], 16, %2;"
                 :: "r"(dst), "l"(src), "r"(sz) : "memory");
}
__device__ __forceinline__ void mma8(float* d, const uint4& a, const uint2& b) {
    asm volatile("mma.sync.aligned.m16n8k8.row.col.f32.tf32.tf32.f32 "
        "{%0,%1,%2,%3}, {%4,%5,%6,%7}, {%8,%9}, {%0,%1,%2,%3};"
        : "+f"(d[0]), "+f"(d[1]), "+f"(d[2]), "+f"(d[3])
        : "r"(a.x), "r"(a.y), "r"(a.z), "r"(a.w), "r"(b.x), "r"(b.y));
}

// ---------------- GEMM core: 128 threads, 64x64 warp tile, 3-stage cp.async ------
// Single-barrier pipeline: wait(1); sync; stage(ic+2); compute(ic).
template<int M, int BMODE, int EPI, bool STATS>
__device__ __forceinline__ void gemm_core(
    const float* __restrict__ A, const float* __restrict__ Bm,
    const float* __restrict__ bias,
    float* __restrict__ out0, float* __restrict__ out1,
    float* __restrict__ ps, float* __restrict__ pq,
    int Kdim, int ROWLEN, int pix0, int co0, int b, int cta, float* sm)
{
    constexpr int WMn = (M == 128) ? 2 : 1;
    constexpr int WNn = 4 / WMn;
    constexpr int MI  = M / (16 * WMn);
    constexpr int NT  = 128 / (8 * WNn);
    constexpr int APITCH = 36;
    constexpr int ABUF = M * APITCH;
    constexpr int BBUF = 128 * APITCH;
    constexpr int STAGE = ABUF + BBUF;

    const int tid = threadIdx.x, lane = tid & 31, warp = tid >> 5;
    const int wm = warp / WNn, wn = warp % WNn;
    const int g = lane >> 2, tig = lane & 3;
    const uint32_t smu = s2u(sm);

    float acc[MI][NT][4] = {};
    const int nch = Kdim >> 5;

    auto stage = [&](int ic) {
        if (ic < nch) {
            const int buf = ic % 3;
            const int k0 = ic << 5;
            uint32_t sA = smu + buf * STAGE * 4;
            uint32_t sB = sA + ABUF * 4;
            #pragma unroll
            for (int i = 0; i < M/16; i++) {            // A: M x 32k
                int idx = tid + i*128;
                int row = idx >> 3, kq = idx & 7;
                cpa16(sA + (row*APITCH + kq*4)*4,
                      A + (size_t)(co0+row)*Kdim + k0 + kq*4, true);
            }
            int ty = 0, tx = 0, ci0 = 0;
            if (BMODE == 1) { int t = k0 >> 8; ty = t/3 - 1; tx = t%3 - 1; ci0 = k0 & 255; }
            #pragma unroll
            for (int i = 0; i < 8; i++) {               // B: 32k x 128pix
                int idx = tid + i*128;
                int pp = idx >> 3, kq = idx & 7;
                uint32_t dst = sB + (pp*APITCH + kq*4)*4;
                if (BMODE == 1) {
                    int pix = pix0 + pp;
                    int py = (pix >> 6) + ty, px = (pix & 63) + tx;
                    bool v = (py >= 0) && (py < 64) && (px >= 0) && (px < 64);
                    cpa16(dst, Bm + ((size_t)b*4096 + (v ? (py*64+px) : 0))*256
                               + ci0 + kq*4, v);
                } else {
                    cpa16(dst, Bm + ((size_t)b*4096 + pix0 + pp)*(size_t)ROWLEN
                               + k0 + kq*4, true);
                }
            }
        }
        asm volatile("cp.async.commit_group;" ::: "memory");
    };

    stage(0);
    stage(1);
    for (int ic = 0; ic < nch; ic++) {
        const int buf = ic % 3;
        asm volatile("cp.async.wait_group 1;" ::: "memory");
        __syncthreads();
        stage(ic + 2);
        const float* sA = sm + buf*STAGE;
        const float* sB = sA + ABUF;
        #pragma unroll
        for (int k8 = 0; k8 < 4; k8++) {
            const int kb = k8 * 8;
            uint4 af[MI];
            #pragma unroll
            for (int mi = 0; mi < MI; mi++) {
                const int cw = wm*(MI*16) + mi*16;
                af[mi].x = __float_as_uint(sA[(cw+g  )*APITCH + kb+tig  ]);
                af[mi].y = __float_as_uint(sA[(cw+g+8)*APITCH + kb+tig  ]);
                af[mi].z = __float_as_uint(sA[(cw+g  )*APITCH + kb+tig+4]);
                af[mi].w = __float_as_uint(sA[(cw+g+8)*APITCH + kb+tig+4]);
            }
            #pragma unroll
            for (int nn = 0; nn < NT; nn++) {
                const int pc = wn*(NT*8) + nn*8 + g;
                uint2 bb;
                bb.x = __float_as_uint(sB[pc*APITCH + kb+tig  ]);
                bb.y = __float_as_uint(sB[pc*APITCH + kb+tig+4]);
                #pragma unroll
                for (int mi = 0; mi < MI; mi++)
                    mma8(acc[mi][nn], af[mi], bb);
            }
        }
    }
    __syncthreads();

    // ---- epilogue (reuses smem) ----
    float* sE = sm;
    if (EPI == 0) {                      // NCHW out; 4 passes over 32-co groups
        #pragma unroll
        for (int p = 0; p < 4; p++) {
            if (wm == (p >> 1)) {
                #pragma unroll
                for (int ml = 0; ml < 2; ml++) {
                    const int mi = (p & 1)*2 + ml;
                    const int r = ml*16 + g;
                    const float b0 = bias[co0 + p*32 + r];
                    const float b1 = bias[co0 + p*32 + r + 8];
                    #pragma unroll
                    for (int nn = 0; nn < NT; nn++) {
                        const int pl = wn*(NT*8) + nn*8 + tig*2;
                        sE[r*132 + pl]       = acc[mi][nn][0] + b0;
                        sE[r*132 + pl+1]     = acc[mi][nn][1] + b0;
                        sE[(r+8)*132 + pl]   = acc[mi][nn][2] + b1;
                        sE[(r+8)*132 + pl+1] = acc[mi][nn][3] + b1;
                    }
                }
            }
            __syncthreads();
            #pragma unroll
            for (int i = 0; i < 8; i++) {
                int idx = tid + i*128;
                int r = idx >> 5, p4 = idx & 31;
                float4 v = *(float4*)&sE[r*132 + p4*4];
                *(float4*)(out0 + (((size_t)b*256 + co0 + p*32 + r) << 12)
                           + pix0 + p4*4) = v;
                if (STATS) {
                    float s  = v.x + v.y + v.z + v.w;
                    float s2 = v.x*v.x + v.y*v.y + v.z*v.z + v.w*v.w;
                    #pragma unroll
                    for (int o = 16; o > 0; o >>= 1) {
                        s  += __shfl_xor_sync(0xffffffffu, s,  o);
                        s2 += __shfl_xor_sync(0xffffffffu, s2, o);
                    }
                    if (lane == 0) {
                        ps[cta*256 + co0 + p*32 + r] = s;
                        pq[cta*256 + co0 + p*32 + r] = s2;
                    }
                }
            }
            __syncthreads();
        }
    } else if (EPI == 1) {               // NHWC out; 2 passes over 64-pix halves
        float sc = 0.f, sc2 = 0.f;
        #pragma unroll
        for (int pass = 0; pass < 2; pass++) {
            if (wn == pass) {
                #pragma unroll
                for (int mi = 0; mi < MI; mi++) {
                    const int r0 = wm*(MI*16) + mi*16 + g;
                    const float b0 = bias[co0 + r0], b1 = bias[co0 + r0 + 8];
                    #pragma unroll
                    for (int nn = 0; nn < NT; nn++) {
                        const int pl = nn*8 + tig*2;
                        sE[pl*132 + r0]       = acc[mi][nn][0] + b0;
                        sE[(pl+1)*132 + r0]   = acc[mi][nn][1] + b0;
                        sE[pl*132 + r0+8]     = acc[mi][nn][2] + b1;
                        sE[(pl+1)*132 + r0+8] = acc[mi][nn][3] + b1;
                    }
                }
            }
            __syncthreads();
            #pragma unroll
            for (int i = 0; i < 16; i++) {
                int idx = tid + i*128;
                int pp = idx >> 5, c4 = idx & 31;
                float4 v = *(float4*)&sE[pp*132 + c4*4];
                *(float4*)(out0 + ((size_t)b*4096 + pix0 + pass*64 + pp)*256
                           + co0 + c4*4) = v;
            }
            if (STATS) {
                #pragma unroll 8
                for (int pp = 0; pp < 64; pp++) {
                    float v = sE[pp*132 + tid];
                    sc += v; sc2 += v*v;
                }
            }
            __syncthreads();
        }
        if (STATS) {
            ps[cta*256 + co0 + tid] = sc;
            pq[cta*256 + co0 + tid] = sc2;
        }
    } else {                             // EPI 2: offsets + mask (M=32, WNn=4)
        #pragma unroll
        for (int mi = 0; mi < MI; mi++)
            #pragma unroll
            for (int nn = 0; nn < NT; nn++) {
                const int r = mi*16 + g;
                const int pl = wn*(NT*8) + nn*8 + tig*2;
                sE[r*132 + pl]       = acc[mi][nn][0];
                sE[r*132 + pl+1]     = acc[mi][nn][1];
                sE[(r+8)*132 + pl]   = acc[mi][nn][2];
                sE[(r+8)*132 + pl+1] = acc[mi][nn][3];
            }
        __syncthreads();
        {
            const int pix = pix0 + tid;
            #pragma unroll
            for (int r = 0; r < 27; r++) {
                float v = sE[r*132 + tid] + bias[r];
                if (r < 18) out0[((size_t)b*18 + r)*4096 + pix] = v;
                else        out1[((size_t)b*9 + r - 18)*4096 + pix] = 2.f/(1.f + expf(-v));
            }
        }
    }
}

// ---------------- GEMM wrappers -------------------------------------------------
__global__ void __launch_bounds__(128, 2) gemm_conv1(
    const float* __restrict__ A, const float* __restrict__ Bm,
    const float* __restrict__ bias, float* __restrict__ out0,
    float* __restrict__ ps, float* __restrict__ pq)
{
    extern __shared__ float sm[];
    gemm_core<128,1,1,true>(A, Bm, bias, out0, nullptr, ps, pq,
        KFULL, 0, blockIdx.x*128, blockIdx.y*128, blockIdx.z,
        blockIdx.x + (blockIdx.z << 5), sm);
}

__global__ void __launch_bounds__(128, 2) gemm_offmod(
    const float* __restrict__ A, const float* __restrict__ Bm,
    const float* __restrict__ bias,
    float* __restrict__ off, float* __restrict__ msk)
{
    extern __shared__ float sm[];
    gemm_core<32,1,2,false>(A, Bm, bias, off, msk, nullptr, nullptr,
        KFULL, 0, blockIdx.x*128, 0, blockIdx.z,
        blockIdx.x + (blockIdx.z << 5), sm);
}

// deform GEMM only (R12 grid form: (32, 2, 8))
__global__ void __launch_bounds__(128, 2) gemm_deform(
    const float* __restrict__ wdp, const float* __restrict__ col,
    const float* __restrict__ b_d, float* __restrict__ d2,
    float* __restrict__ ps1, float* __restrict__ pq1)
{
    extern __shared__ float sm[];
    gemm_core<128,0,0,true>(wdp, col, b_d, d2, nullptr, ps1, pq1,
        KFULL, KFULL, blockIdx.x*128, blockIdx.y*128, blockIdx.z,
        blockIdx.x + (blockIdx.z << 5), sm);
}

// ---------------- merged: 1x1 GEMM (512 blocks FIRST) + deformable gather --------
// Blocks [0,512): 1x1 shortcut (tensor-bound). Blocks [512, 512+32768): sample
// (L2-bound). GEMM blocks first in dispatch order -> they hold SMs while sample
// blocks stream through remaining slots: the 1x1's time hides inside sample's.
__global__ void __launch_bounds__(128, 2) sample_1x1(
    const float* __restrict__ y1h, const float* __restrict__ off,
    const float* __restrict__ msk, float* __restrict__ col,
    const float* __restrict__ wds, const float* __restrict__ xt,
    const float* __restrict__ b_ds, float* __restrict__ res,
    float* __restrict__ ps2, float* __restrict__ pq2)
{
    extern __shared__ float sm[];
    const int bx = blockIdx.x;
    if (bx < 512) {                       // 32 pix-blocks x 2 co-halves x 8 batches
        const int pb = bx & 31, half = (bx >> 5) & 1, b = bx >> 6;
        gemm_core<128,0,0,true>(wds, xt, b_ds, res, nullptr, ps2, pq2,
            256, 256, pb*128, half*128, b, pb + (b << 5), sm);
        return;
    }
    const int i = bx - 512;
    const int pix = i & 4095, b = i >> 12;
    const int wp = threadIdx.x >> 5, lane = threadIdx.x & 31;
    const int ho = pix >> 6, wo = pix & 63;
    const float* base = y1h + (size_t)b*4096*256;

    for (int p = wp; p < 9; p += 4) {
        const float dy = off[((size_t)b*18 + 2*p    )*4096 + pix];
        const float dx = off[((size_t)b*18 + 2*p + 1)*4096 + pix];
        const float m  = msk[((size_t)b*9 + p)*4096 + pix];
        const float py = (float)(ho - 1 + p/3) + dy;
        const float px = (float)(wo - 1 + p%3) + dx;

        const float y0f = floorf(py), x0f = floorf(px);
        const float ly = py - y0f, lx = px - x0f;
        const int y0 = (int)y0f, x0 = (int)x0f;
        const int y1 = y0 + 1,  x1 = x0 + 1;
        float w00 = (1.f-ly)*(1.f-lx), w01 = (1.f-ly)*lx, w10 = ly*(1.f-lx), w11 = ly*lx;
        const bool vy0 = (y0 >= 0) && (y0 < 64), vy1 = (y1 >= 0) && (y1 < 64);
        const bool vx0 = (x0 >= 0) && (x0 < 64), vx1 = (x1 >= 0) && (x1 < 64);
        if (!(vy0 && vx0)) w00 = 0.f;
        if (!(vy0 && vx1)) w01 = 0.f;
        if (!(vy1 && vx0)) w10 = 0.f;
        if (!(vy1 && vx1)) w11 = 0.f;
        const int yc0 = min(max(y0, 0), 63), yc1 = min(max(y1, 0), 63);
        const int xc0 = min(max(x0, 0), 63), xc1 = min(max(x1, 0), 63);
        w00 *= m; w01 *= m; w10 *= m; w11 *= m;

        const float* p00 = base + (size_t)(yc0*64 + xc0)*256 + lane*8;
        const float* p01 = base + (size_t)(yc0*64 + xc1)*256 + lane*8;
        const float* p10 = base + (size_t)(yc1*64 + xc0)*256 + lane*8;
        const float* p11 = base + (size_t)(yc1*64 + xc1)*256 + lane*8;
        float* cp = col + ((size_t)b*4096 + pix)*KFULL + p*256 + lane*8;

        #pragma unroll
        for (int h = 0; h < 2; h++) {
            const float4 a = *(const float4*)(p00 + h*4);
            const float4 c2 = *(const float4*)(p01 + h*4);
            const float4 d = *(const float4*)(p10 + h*4);
            const float4 e = *(const float4*)(p11 + h*4);
            float4 s;
            s.x = f2tff(w00*a.x + w01*c2.x + w10*d.x + w11*e.x);
            s.y = f2tff(w00*a.y + w01*c2.y + w10*d.y + w11*e.y);
            s.z = f2tff(w00*a.z + w01*c2.z + w10*d.z + w11*e.z);
            s.w = f2tff(w00*a.w + w01*c2.w + w10*d.w + w11*e.w);
            *(float4*)(cp + h*4) = s;
        }
    }
}

// ---------------- stats combine -------------------------------------------------
__global__ __launch_bounds__(256) void bn_combine(const float* __restrict__ ps,
    const float* __restrict__ pq, float* __restrict__ st)
{
    const int c = threadIdx.x;
    float s = 0.f, s2 = 0.f;
    #pragma unroll 8
    for (int j = 0; j < 256; j++) { s += ps[j*256 + c]; s2 += pq[j*256 + c]; }
    const float m = s * (1.f/32768.f);
    const float var = s2 * (1.f/32768.f) - m*m;
    st[c] = m;
    st[256 + c] = rsqrtf(var + 1e-5f);
}

__global__ __launch_bounds__(256) void bn_combine_pair(const float* __restrict__ ps,
    const float* __restrict__ pq, float* __restrict__ st)
{
    const int sel = blockIdx.x;                       // 0: deform, 1: 1x1
    const float* p = ps + (sel+1)*65536;
    const float* q = pq + (sel+1)*65536;
    const int c = threadIdx.x;
    float s = 0.f, s2 = 0.f;
    #pragma unroll 8
    for (int j = 0; j < 256; j++) { s += p[j*256 + c]; s2 += q[j*256 + c]; }
    const float m = s * (1.f/32768.f);
    const float var = s2 * (1.f/32768.f) - m*m;
    st[512 + sel*512 + c] = m;
    st[768 + sel*512 + c] = rsqrtf(var + 1e-5f);
}

// ---------------- merged prep kernel ---------------------------------------------
__global__ __launch_bounds__(256) void prep_all(
    const float* __restrict__ x, float* __restrict__ xt,
    const float* __restrict__ w1, float* __restrict__ w1p,
    const float* __restrict__ w_d, float* __restrict__ wdp,
    const float* __restrict__ w_off, const float* __restrict__ w_mod,
    const float* __restrict__ b_off, const float* __restrict__ b_mod,
    float* __restrict__ wop, float* __restrict__ bp,
    const float* __restrict__ w_ds, float* __restrict__ wds)
{
    __shared__ float tb[32][33];
    const int bx = blockIdx.x;
    if (bx < 8192) {                                  // NCHW->NHWC round of x
        const int b = bx >> 10, cy = (bx >> 7) & 7, cx = bx & 127;
        const int pix0 = cx*32, c0 = cy*32;
        const int tx = threadIdx.x & 31, ty = threadIdx.x >> 5;
        #pragma unroll
        for (int i = 0; i < 4; i++)
            tb[ty + i*8][tx] = f2tff(x[((size_t)b*256 + c0 + ty + i*8)*4096 + pix0 + tx]);
        __syncthreads();
        #pragma unroll
        for (int i = 0; i < 4; i++)
            xt[((size_t)b*4096 + pix0 + ty + i*8)*256 + c0 + tx] = tb[tx][ty + i*8];
    } else if (bx < 8192 + 2304) {                    // permute w1
        int i = (bx - 8192)*256 + threadIdx.x;
        int co = i / KFULL, r = i - co*KFULL;
        int t = r >> 8, ci = r & 255;
        w1p[i] = f2tff(w1[co*KFULL + ci*9 + t]);
    } else if (bx < 8192 + 4608) {                    // permute w_d
        int i = (bx - 8192 - 2304)*256 + threadIdx.x;
        int co = i / KFULL, r = i - co*KFULL;
        int t = r >> 8, ci = r & 255;
        wdp[i] = f2tff(w_d[co*KFULL + ci*9 + t]);
    } else if (bx < 8192 + 4896) {                    // pack offmod
        int i = (bx - 8192 - 4608)*256 + threadIdx.x;
        if (i < 32*KFULL) {
            int o = i / KFULL, r = i - o*KFULL;
            int t = r >> 8, ci = r & 255;
            float v = 0.f;
            if (o < 18)      v = w_off[o*KFULL + ci*9 + t];
            else if (o < 27) v = w_mod[(o-18)*KFULL + ci*9 + t];
            wop[i] = f2tff(v);
        }
        if (i < 27) bp[i] = (i < 18) ? b_off[i] : b_mod[i-18];
    } else {                                          // round w_ds
        int i = (bx - 8192 - 4896)*256 + threadIdx.x;
        wds[i] = f2tff(w_ds[i]);
    }
}

// in-place BN + ReLU + tf32 round on NHWC, float4
__global__ __launch_bounds__(256) void bn_relu_nhwc(float* __restrict__ y,
    const float* __restrict__ st, const float* __restrict__ g, const float* __restrict__ bt)
{
    const int i4 = blockIdx.x*256 + threadIdx.x;     // float4 index
    const int c0 = (i4 & 63) * 4;
    const float4 mn = *(const float4*)(st + c0);
    const float4 rs = *(const float4*)(st + 256 + c0);
    const float4 gg = *(const float4*)(g + c0);
    const float4 bb = *(const float4*)(bt + c0);
    float4 v = *(float4*)(y + (size_t)i4*4);
    v.x = f2tff(fmaxf((v.x - mn.x)*rs.x*gg.x + bb.x, 0.f));
    v.y = f2tff(fmaxf((v.y - mn.y)*rs.y*gg.y + bb.y, 0.f));
    v.z = f2tff(fmaxf((v.z - mn.z)*rs.z*gg.z + bb.z, 0.f));
    v.w = f2tff(fmaxf((v.w - mn.w)*rs.w*gg.w + bb.w, 0.f));
    *(float4*)(y + (size_t)i4*4) = v;
}

// ---------------- final: relu( bn2(d2) + bn3(res) ), float4 ------------------------
__global__ __launch_bounds__(256) void final_fuse(
    const float* __restrict__ d2, const float* __restrict__ res,
    const float* __restrict__ st,
    const float* __restrict__ g2, const float* __restrict__ bt2,
    const float* __restrict__ g3, const float* __restrict__ bt3,
    float* __restrict__ out)
{
    const int i4 = blockIdx.x*256 + threadIdx.x;     // float4 index
    const int c = (i4 >> 10) & 255;
    const float a2 = st[768 + c]  * g2[c];
    const float a3 = st[1280 + c] * g3[c];
    const float k2 = bt2[c] - st[512 + c]  * a2;
    const float k3 = bt3[c] - st[1024 + c] * a3;
    const float4 dv = *(const float4*)(d2  + (size_t)i4*4);
    const float4 rv = *(const float4*)(res + (size_t)i4*4);
    float4 o;
    o.x = fmaxf(dv.x*a2 + k2 + rv.x*a3 + k3, 0.f);
    o.y = fmaxf(dv.y*a2 + k2 + rv.y*a3 + k3, 0.f);
    o.z = fmaxf(dv.z*a2 + k2 + rv.z*a3 + k3, 0.f);
    o.w = fmaxf(dv.w*a2 + k2 + rv.w*a3 + k3, 0.f);
    *(float4*)(out + (size_t)i4*4) = o;
}

// ---------------- launcher -----------------------------------------------------------
extern "C" void kernel_launch(void* const* d_in, const int* in_sizes, int n_in,
                              void* d_out, int out_size)
{
    const float* x     = (const float*)d_in[0];
    const float* w1    = (const float*)d_in[2];
    const float* b1    = (const float*)d_in[3];
    const float* g1    = (const float*)d_in[4];
    const float* bt1   = (const float*)d_in[5];
    const float* w_off = (const float*)d_in[6];
    const float* b_off = (const float*)d_in[7];
    const float* w_mod = (const float*)d_in[8];
    const float* b_mod = (const float*)d_in[9];
    const float* w_d   = (const float*)d_in[10];
    const float* b_d   = (const float*)d_in[11];
    const float* g2    = (const float*)d_in[12];
    const float* bt2   = (const float*)d_in[13];
    const float* w_ds  = (const float*)d_in[14];
    const float* b_ds  = (const float*)d_in[15];
    const float* g3    = (const float*)d_in[16];
    const float* bt3   = (const float*)d_in[17];

    float *xt, *y1h, *d2, *res, *off, *msk, *col, *st, *ps, *pq;
    float *w1p, *wdp, *wop, *wds, *bp;
    cudaGetSymbolAddress((void**)&xt,  g_xt);
    cudaGetSymbolAddress((void**)&y1h, g_y1h);
    cudaGetSymbolAddress((void**)&d2,  g_d2);
    cudaGetSymbolAddress((void**)&res, g_res);
    cudaGetSymbolAddress((void**)&off, g_off);
    cudaGetSymbolAddress((void**)&msk, g_mask);
    cudaGetSymbolAddress((void**)&col, g_col);
    cudaGetSymbolAddress((void**)&st,  g_stats);
    cudaGetSymbolAddress((void**)&ps,  g_ps);
    cudaGetSymbolAddress((void**)&pq,  g_pq);
    cudaGetSymbolAddress((void**)&w1p, g_w1p);
    cudaGetSymbolAddress((void**)&wdp, g_wdp);
    cudaGetSymbolAddress((void**)&wop, g_wop);
    cudaGetSymbolAddress((void**)&wds, g_wds);
    cudaGetSymbolAddress((void**)&bp,  g_bp);

    const int SM128 = 3 * (128*36 + 128*36) * 4;   // 110592
    const int SM32  = 3 * (32*36  + 128*36) * 4;   // 69120
    cudaFuncSetAttribute(gemm_conv1,  cudaFuncAttributeMaxDynamicSharedMemorySize, SM128);
    cudaFuncSetAttribute(gemm_deform, cudaFuncAttributeMaxDynamicSharedMemorySize, SM128);
    cudaFuncSetAttribute(sample_1x1,  cudaFuncAttributeMaxDynamicSharedMemorySize, SM128);
    cudaFuncSetAttribute(gemm_offmod, cudaFuncAttributeMaxDynamicSharedMemorySize, SM32);

    // 0) merged prep: NHWC x, all weight permutes/rounds
    prep_all<<<13344, 256>>>(x, xt, w1, w1p, w_d, wdp,
                             w_off, w_mod, b_off, b_mod, wop, bp, w_ds, wds);
    // 1) conv1: implicit 3x3 GEMM -> y1h NHWC raw + fused stats partials
    gemm_conv1<<<dim3(32, 2, BN), 128, SM128>>>(w1p, xt, b1, y1h, ps, pq);
    bn_combine<<<1, 256>>>(ps, pq, st);
    // 2) BN1 + ReLU + round, in place (float4)
    bn_relu_nhwc<<<(int)((size_t)BN*HWn*C/1024), 256>>>(y1h, st, g1, bt1);
    // 3) offsets + modulation
    gemm_offmod<<<dim3(32, 1, BN), 128, SM32>>>(wop, y1h, bp, off, msk);
    // 4) 1x1 shortcut GEMM (tensor) co-scheduled with bilinear gather (L2)
    sample_1x1<<<512 + BN*HWn, 128, SM128>>>(y1h, off, msk, col,
        wds, xt, b_ds, res, ps + 2*65536, pq + 2*65536);
    // 5) deform GEMM (K=2304)
    gemm_deform<<<dim3(32, 2, BN), 128, SM128>>>(
        wdp, col, b_d, d2, ps + 65536, pq + 65536);
    bn_combine_pair<<<2, 256>>>(ps, pq, st);
    // 6) fused BN2 + BN3 + add + ReLU (vectorized)
    final_fuse<<<BN*C*HWn/1024, 256>>>(d2, res, st, g2, bt2, g3, bt3, (float*)d_out);
}

// round 15
// speedup vs baseline: 1.2732x; 1.2732x over previous
#include <cuda_runtime.h>
#include <math.h>
#include <stdint.h>

#define BN 8
#define C 256
#define HWn 4096
#define KFULL 2304

// ---------------- scratch (device globals: allocation-free) ----------------
__device__ float g_xt [(size_t)BN*HWn*C];        // x NHWC, tf32-rounded
__device__ float g_y1h[(size_t)BN*HWn*C];        // conv1 NHWC raw -> (in place) bn+relu rounded
__device__ float g_d2 [(size_t)BN*C*HWn];        // deform conv raw NCHW
__device__ float g_res[(size_t)BN*C*HWn];        // 1x1 raw NCHW
__device__ float g_off[BN*18*HWn];
__device__ float g_mask[BN*9*HWn];
__device__ float g_col[(size_t)BN*HWn*KFULL];    // [b][pix][k=p*256+ci], rounded
__device__ float g_stats[6*256];
__device__ float g_ps[3*256*256];                // [cta][c]
__device__ float g_pq[3*256*256];
__device__ float g_w1p[256*KFULL];
__device__ float g_wdp[256*KFULL];
__device__ float g_wop[32*KFULL];
__device__ float g_wds[256*256];
__device__ float g_bp[32];

// ---------------- helpers -----------------------------------------------------
__device__ __forceinline__ unsigned f2tf(float v) {
    unsigned u; asm("cvt.rna.tf32.f32 %0, %1;" : "=r"(u) : "f"(v)); return u;
}
__device__ __forceinline__ float f2tff(float v) { return __uint_as_float(f2tf(v)); }
__device__ __forceinline__ uint32_t s2u(const void* p) {
    uint32_t a;
    asm("{ .reg .u64 t; cvta.to.shared.u64 t, %1; cvt.u32.u64 %0, t; }" : "=r"(a) : "l"(p));
    return a;
}
__device__ __forceinline__ void cpa16(uint32_t dst, const void* src, bool v) {
    int sz = v ? 16 : 0;
    asm volatile("cp.async.cg.shared.global [%0], [%1], 16, %2;"
                 :: "r"(dst), "l"(src), "r"(sz) : "memory");
}
__device__ __forceinline__ void mma8(float* d, const uint4& a, const uint2& b) {
    asm volatile("mma.sync.aligned.m16n8k8.row.col.f32.tf32.tf32.f32 "
        "{%0,%1,%2,%3}, {%4,%5,%6,%7}, {%8,%9}, {%0,%1,%2,%3};"
        : "+f"(d[0]), "+f"(d[1]), "+f"(d[2]), "+f"(d[3])
        : "r"(a.x), "r"(a.y), "r"(a.z), "r"(a.w), "r"(b.x), "r"(b.y));
}

// ---------------- GEMM core: 128 threads, 64x64 warp tile, 3-stage cp.async ------
// Single-barrier pipeline: wait(1); sync; stage(ic+2); compute(ic).
template<int M, int BMODE, int EPI, bool STATS>
__device__ __forceinline__ void gemm_core(
    const float* __restrict__ A, const float* __restrict__ Bm,
    const float* __restrict__ bias,
    float* __restrict__ out0, float* __restrict__ out1,
    float* __restrict__ ps, float* __restrict__ pq,
    int Kdim, int ROWLEN, int pix0, int co0, int b, int cta, float* sm)
{
    constexpr int WMn = (M == 128) ? 2 : 1;
    constexpr int WNn = 4 / WMn;
    constexpr int MI  = M / (16 * WMn);
    constexpr int NT  = 128 / (8 * WNn);
    constexpr int APITCH = 36;
    constexpr int ABUF = M * APITCH;
    constexpr int BBUF = 128 * APITCH;
    constexpr int STAGE = ABUF + BBUF;

    const int tid = threadIdx.x, lane = tid & 31, warp = tid >> 5;
    const int wm = warp / WNn, wn = warp % WNn;
    const int g = lane >> 2, tig = lane & 3;
    const uint32_t smu = s2u(sm);

    float acc[MI][NT][4] = {};
    const int nch = Kdim >> 5;

    auto stage = [&](int ic) {
        if (ic < nch) {
            const int buf = ic % 3;
            const int k0 = ic << 5;
            uint32_t sA = smu + buf * STAGE * 4;
            uint32_t sB = sA + ABUF * 4;
            #pragma unroll
            for (int i = 0; i < M/16; i++) {            // A: M x 32k
                int idx = tid + i*128;
                int row = idx >> 3, kq = idx & 7;
                cpa16(sA + (row*APITCH + kq*4)*4,
                      A + (size_t)(co0+row)*Kdim + k0 + kq*4, true);
            }
            int ty = 0, tx = 0, ci0 = 0;
            if (BMODE == 1) { int t = k0 >> 8; ty = t/3 - 1; tx = t%3 - 1; ci0 = k0 & 255; }
            #pragma unroll
            for (int i = 0; i < 8; i++) {               // B: 32k x 128pix
                int idx = tid + i*128;
                int pp = idx >> 3, kq = idx & 7;
                uint32_t dst = sB + (pp*APITCH + kq*4)*4;
                if (BMODE == 1) {
                    int pix = pix0 + pp;
                    int py = (pix >> 6) + ty, px = (pix & 63) + tx;
                    bool v = (py >= 0) && (py < 64) && (px >= 0) && (px < 64);
                    cpa16(dst, Bm + ((size_t)b*4096 + (v ? (py*64+px) : 0))*256
                               + ci0 + kq*4, v);
                } else {
                    cpa16(dst, Bm + ((size_t)b*4096 + pix0 + pp)*(size_t)ROWLEN
                               + k0 + kq*4, true);
                }
            }
        }
        asm volatile("cp.async.commit_group;" ::: "memory");
    };

    stage(0);
    stage(1);
    for (int ic = 0; ic < nch; ic++) {
        const int buf = ic % 3;
        asm volatile("cp.async.wait_group 1;" ::: "memory");
        __syncthreads();
        stage(ic + 2);
        const float* sA = sm + buf*STAGE;
        const float* sB = sA + ABUF;
        #pragma unroll
        for (int k8 = 0; k8 < 4; k8++) {
            const int kb = k8 * 8;
            uint4 af[MI];
            #pragma unroll
            for (int mi = 0; mi < MI; mi++) {
                const int cw = wm*(MI*16) + mi*16;
                af[mi].x = __float_as_uint(sA[(cw+g  )*APITCH + kb+tig  ]);
                af[mi].y = __float_as_uint(sA[(cw+g+8)*APITCH + kb+tig  ]);
                af[mi].z = __float_as_uint(sA[(cw+g  )*APITCH + kb+tig+4]);
                af[mi].w = __float_as_uint(sA[(cw+g+8)*APITCH + kb+tig+4]);
            }
            #pragma unroll
            for (int nn = 0; nn < NT; nn++) {
                const int pc = wn*(NT*8) + nn*8 + g;
                uint2 bb;
                bb.x = __float_as_uint(sB[pc*APITCH + kb+tig  ]);
                bb.y = __float_as_uint(sB[pc*APITCH + kb+tig+4]);
                #pragma unroll
                for (int mi = 0; mi < MI; mi++)
                    mma8(acc[mi][nn], af[mi], bb);
            }
        }
    }
    __syncthreads();

    // ---- epilogue (reuses smem) ----
    float* sE = sm;
    if (EPI == 0) {                      // NCHW out; 4 passes over 32-co groups
        #pragma unroll
        for (int p = 0; p < 4; p++) {
            if (wm == (p >> 1)) {
                #pragma unroll
                for (int ml = 0; ml < 2; ml++) {
                    const int mi = (p & 1)*2 + ml;
                    const int r = ml*16 + g;
                    const float b0 = bias[co0 + p*32 + r];
                    const float b1 = bias[co0 + p*32 + r + 8];
                    #pragma unroll
                    for (int nn = 0; nn < NT; nn++) {
                        const int pl = wn*(NT*8) + nn*8 + tig*2;
                        sE[r*132 + pl]       = acc[mi][nn][0] + b0;
                        sE[r*132 + pl+1]     = acc[mi][nn][1] + b0;
                        sE[(r+8)*132 + pl]   = acc[mi][nn][2] + b1;
                        sE[(r+8)*132 + pl+1] = acc[mi][nn][3] + b1;
                    }
                }
            }
            __syncthreads();
            #pragma unroll
            for (int i = 0; i < 8; i++) {
                int idx = tid + i*128;
                int r = idx >> 5, p4 = idx & 31;
                float4 v = *(float4*)&sE[r*132 + p4*4];
                *(float4*)(out0 + (((size_t)b*256 + co0 + p*32 + r) << 12)
                           + pix0 + p4*4) = v;
                if (STATS) {
                    float s  = v.x + v.y + v.z + v.w;
                    float s2 = v.x*v.x + v.y*v.y + v.z*v.z + v.w*v.w;
                    #pragma unroll
                    for (int o = 16; o > 0; o >>= 1) {
                        s  += __shfl_xor_sync(0xffffffffu, s,  o);
                        s2 += __shfl_xor_sync(0xffffffffu, s2, o);
                    }
                    if (lane == 0) {
                        ps[cta*256 + co0 + p*32 + r] = s;
                        pq[cta*256 + co0 + p*32 + r] = s2;
                    }
                }
            }
            __syncthreads();
        }
    } else if (EPI == 1) {               // NHWC out; 2 passes over 64-pix halves
        float sc = 0.f, sc2 = 0.f;
        #pragma unroll
        for (int pass = 0; pass < 2; pass++) {
            if (wn == pass) {
                #pragma unroll
                for (int mi = 0; mi < MI; mi++) {
                    const int r0 = wm*(MI*16) + mi*16 + g;
                    const float b0 = bias[co0 + r0], b1 = bias[co0 + r0 + 8];
                    #pragma unroll
                    for (int nn = 0; nn < NT; nn++) {
                        const int pl = nn*8 + tig*2;
                        sE[pl*132 + r0]       = acc[mi][nn][0] + b0;
                        sE[(pl+1)*132 + r0]   = acc[mi][nn][1] + b0;
                        sE[pl*132 + r0+8]     = acc[mi][nn][2] + b1;
                        sE[(pl+1)*132 + r0+8] = acc[mi][nn][3] + b1;
                    }
                }
            }
            __syncthreads();
            #pragma unroll
            for (int i = 0; i < 16; i++) {
                int idx = tid + i*128;
                int pp = idx >> 5, c4 = idx & 31;
                float4 v = *(float4*)&sE[pp*132 + c4*4];
                *(float4*)(out0 + ((size_t)b*4096 + pix0 + pass*64 + pp)*256
                           + co0 + c4*4) = v;
            }
            if (STATS) {
                #pragma unroll 8
                for (int pp = 0; pp < 64; pp++) {
                    float v = sE[pp*132 + tid];
                    sc += v; sc2 += v*v;
                }
            }
            __syncthreads();
        }
        if (STATS) {
            ps[cta*256 + co0 + tid] = sc;
            pq[cta*256 + co0 + tid] = sc2;
        }
    } else {                             // EPI 2: offsets + mask (M=32, WNn=4)
        #pragma unroll
        for (int mi = 0; mi < MI; mi++)
            #pragma unroll
            for (int nn = 0; nn < NT; nn++) {
                const int r = mi*16 + g;
                const int pl = wn*(NT*8) + nn*8 + tig*2;
                sE[r*132 + pl]       = acc[mi][nn][0];
                sE[r*132 + pl+1]     = acc[mi][nn][1];
                sE[(r+8)*132 + pl]   = acc[mi][nn][2];
                sE[(r+8)*132 + pl+1] = acc[mi][nn][3];
            }
        __syncthreads();
        {
            const int pix = pix0 + tid;
            #pragma unroll
            for (int r = 0; r < 27; r++) {
                float v = sE[r*132 + tid] + bias[r];
                if (r < 18) out0[((size_t)b*18 + r)*4096 + pix] = v;
                else        out1[((size_t)b*9 + r - 18)*4096 + pix] = 2.f/(1.f + expf(-v));
            }
        }
    }
}

// ---------------- GEMM wrappers -------------------------------------------------
__global__ void __launch_bounds__(128, 2) gemm_conv1(
    const float* __restrict__ A, const float* __restrict__ Bm,
    const float* __restrict__ bias, float* __restrict__ out0,
    float* __restrict__ ps, float* __restrict__ pq)
{
    extern __shared__ float sm[];
    gemm_core<128,1,1,true>(A, Bm, bias, out0, nullptr, ps, pq,
        KFULL, 0, blockIdx.x*128, blockIdx.y*128, blockIdx.z,
        blockIdx.x + (blockIdx.z << 5), sm);
}

__global__ void __launch_bounds__(128, 2) gemm_offmod(
    const float* __restrict__ A, const float* __restrict__ Bm,
    const float* __restrict__ bias,
    float* __restrict__ off, float* __restrict__ msk)
{
    extern __shared__ float sm[];
    gemm_core<32,1,2,false>(A, Bm, bias, off, msk, nullptr, nullptr,
        KFULL, 0, blockIdx.x*128, 0, blockIdx.z,
        blockIdx.x + (blockIdx.z << 5), sm);
}

// y<2: deform GEMM (K=2304, B=col).  y>=2: 1x1 shortcut (K=256, B=xt).  (R12 form)
__global__ void __launch_bounds__(128, 2) gemm_dual(
    const float* __restrict__ wdp, const float* __restrict__ col,
    const float* __restrict__ b_d, float* __restrict__ d2,
    float* __restrict__ ps1, float* __restrict__ pq1,
    const float* __restrict__ wds, const float* __restrict__ xt,
    const float* __restrict__ b_ds, float* __restrict__ res,
    float* __restrict__ ps2, float* __restrict__ pq2)
{
    extern __shared__ float sm[];
    const int pix0 = blockIdx.x*128, b = blockIdx.z;
    const int cta = blockIdx.x + (blockIdx.z << 5);
    if (blockIdx.y < 2)
        gemm_core<128,0,0,true>(wdp, col, b_d, d2, nullptr, ps1, pq1,
            KFULL, KFULL, pix0, blockIdx.y*128, b, cta, sm);
    else
        gemm_core<128,0,0,true>(wds, xt, b_ds, res, nullptr, ps2, pq2,
            256, 256, pix0, (blockIdx.y-2)*128, b, cta, sm);
}

// ---------------- stats combine -------------------------------------------------
__global__ __launch_bounds__(256) void bn_combine(const float* __restrict__ ps,
    const float* __restrict__ pq, float* __restrict__ st)
{
    const int c = threadIdx.x;
    float s = 0.f, s2 = 0.f;
    #pragma unroll 8
    for (int j = 0; j < 256; j++) { s += ps[j*256 + c]; s2 += pq[j*256 + c]; }
    const float m = s * (1.f/32768.f);
    const float var = s2 * (1.f/32768.f) - m*m;
    st[c] = m;
    st[256 + c] = rsqrtf(var + 1e-5f);
}

__global__ __launch_bounds__(256) void bn_combine_pair(const float* __restrict__ ps,
    const float* __restrict__ pq, float* __restrict__ st)
{
    const int sel = blockIdx.x;                       // 0: deform, 1: 1x1
    const float* p = ps + (sel+1)*65536;
    const float* q = pq + (sel+1)*65536;
    const int c = threadIdx.x;
    float s = 0.f, s2 = 0.f;
    #pragma unroll 8
    for (int j = 0; j < 256; j++) { s += p[j*256 + c]; s2 += q[j*256 + c]; }
    const float m = s * (1.f/32768.f);
    const float var = s2 * (1.f/32768.f) - m*m;
    st[512 + sel*512 + c] = m;
    st[768 + sel*512 + c] = rsqrtf(var + 1e-5f);
}

// ---------------- merged prep kernel ---------------------------------------------
__global__ __launch_bounds__(256) void prep_all(
    const float* __restrict__ x, float* __restrict__ xt,
    const float* __restrict__ w1, float* __restrict__ w1p,
    const float* __restrict__ w_d, float* __restrict__ wdp,
    const float* __restrict__ w_off, const float* __restrict__ w_mod,
    const float* __restrict__ b_off, const float* __restrict__ b_mod,
    float* __restrict__ wop, float* __restrict__ bp,
    const float* __restrict__ w_ds, float* __restrict__ wds)
{
    __shared__ float tb[32][33];
    const int bx = blockIdx.x;
    if (bx < 8192) {                                  // NCHW->NHWC round of x
        const int b = bx >> 10, cy = (bx >> 7) & 7, cx = bx & 127;
        const int pix0 = cx*32, c0 = cy*32;
        const int tx = threadIdx.x & 31, ty = threadIdx.x >> 5;
        #pragma unroll
        for (int i = 0; i < 4; i++)
            tb[ty + i*8][tx] = f2tff(x[((size_t)b*256 + c0 + ty + i*8)*4096 + pix0 + tx]);
        __syncthreads();
        #pragma unroll
        for (int i = 0; i < 4; i++)
            xt[((size_t)b*4096 + pix0 + ty + i*8)*256 + c0 + tx] = tb[tx][ty + i*8];
    } else if (bx < 8192 + 2304) {                    // permute w1
        int i = (bx - 8192)*256 + threadIdx.x;
        int co = i / KFULL, r = i - co*KFULL;
        int t = r >> 8, ci = r & 255;
        w1p[i] = f2tff(w1[co*KFULL + ci*9 + t]);
    } else if (bx < 8192 + 4608) {                    // permute w_d
        int i = (bx - 8192 - 2304)*256 + threadIdx.x;
        int co = i / KFULL, r = i - co*KFULL;
        int t = r >> 8, ci = r & 255;
        wdp[i] = f2tff(w_d[co*KFULL + ci*9 + t]);
    } else if (bx < 8192 + 4896) {                    // pack offmod
        int i = (bx - 8192 - 4608)*256 + threadIdx.x;
        if (i < 32*KFULL) {
            int o = i / KFULL, r = i - o*KFULL;
            int t = r >> 8, ci = r & 255;
            float v = 0.f;
            if (o < 18)      v = w_off[o*KFULL + ci*9 + t];
            else if (o < 27) v = w_mod[(o-18)*KFULL + ci*9 + t];
            wop[i] = f2tff(v);
        }
        if (i < 27) bp[i] = (i < 18) ? b_off[i] : b_mod[i-18];
    } else {                                          // round w_ds
        int i = (bx - 8192 - 4896)*256 + threadIdx.x;
        wds[i] = f2tff(w_ds[i]);
    }
}

// in-place BN + ReLU + tf32 round on NHWC, float4 (measured: 12.2us)
__global__ __launch_bounds__(256) void bn_relu_nhwc(float* __restrict__ y,
    const float* __restrict__ st, const float* __restrict__ g, const float* __restrict__ bt)
{
    const int i4 = blockIdx.x*256 + threadIdx.x;     // float4 index
    const int c0 = (i4 & 63) * 4;
    const float4 mn = *(const float4*)(st + c0);
    const float4 rs = *(const float4*)(st + 256 + c0);
    const float4 gg = *(const float4*)(g + c0);
    const float4 bb = *(const float4*)(bt + c0);
    float4 v = *(float4*)(y + (size_t)i4*4);
    v.x = f2tff(fmaxf((v.x - mn.x)*rs.x*gg.x + bb.x, 0.f));
    v.y = f2tff(fmaxf((v.y - mn.y)*rs.y*gg.y + bb.y, 0.f));
    v.z = f2tff(fmaxf((v.z - mn.z)*rs.z*gg.z + bb.z, 0.f));
    v.w = f2tff(fmaxf((v.w - mn.w)*rs.w*gg.w + bb.w, 0.f));
    *(float4*)(y + (size_t)i4*4) = v;
}

// ---------------- deformable gather on NHWC -> col [b][pix][k] -------------------
__global__ __launch_bounds__(288) void deform_sample(
    const float* __restrict__ y1h, const float* __restrict__ off,
    const float* __restrict__ msk, float* __restrict__ col)
{
    const int p = threadIdx.x >> 5, lane = threadIdx.x & 31;
    const int pix = blockIdx.x, b = blockIdx.y;
    const int ho = pix >> 6, wo = pix & 63;

    const float dy = off[((size_t)b*18 + 2*p    )*4096 + pix];
    const float dx = off[((size_t)b*18 + 2*p + 1)*4096 + pix];
    const float m  = msk[((size_t)b*9 + p)*4096 + pix];
    const float py = (float)(ho - 1 + p/3) + dy;
    const float px = (float)(wo - 1 + p%3) + dx;

    const float y0f = floorf(py), x0f = floorf(px);
    const float ly = py - y0f, lx = px - x0f;
    const int y0 = (int)y0f, x0 = (int)x0f;
    const int y1 = y0 + 1,  x1 = x0 + 1;
    float w00 = (1.f-ly)*(1.f-lx), w01 = (1.f-ly)*lx, w10 = ly*(1.f-lx), w11 = ly*lx;
    const bool vy0 = (y0 >= 0) && (y0 < 64), vy1 = (y1 >= 0) && (y1 < 64);
    const bool vx0 = (x0 >= 0) && (x0 < 64), vx1 = (x1 >= 0) && (x1 < 64);
    if (!(vy0 && vx0)) w00 = 0.f;
    if (!(vy0 && vx1)) w01 = 0.f;
    if (!(vy1 && vx0)) w10 = 0.f;
    if (!(vy1 && vx1)) w11 = 0.f;
    const int yc0 = min(max(y0, 0), 63), yc1 = min(max(y1, 0), 63);
    const int xc0 = min(max(x0, 0), 63), xc1 = min(max(x1, 0), 63);
    w00 *= m; w01 *= m; w10 *= m; w11 *= m;

    const float* base = y1h + (size_t)b*4096*256;
    const float* p00 = base + (size_t)(yc0*64 + xc0)*256 + lane*8;
    const float* p01 = base + (size_t)(yc0*64 + xc1)*256 + lane*8;
    const float* p10 = base + (size_t)(yc1*64 + xc0)*256 + lane*8;
    const float* p11 = base + (size_t)(yc1*64 + xc1)*256 + lane*8;
    float* cp = col + ((size_t)b*4096 + pix)*KFULL + p*256 + lane*8;

    #pragma unroll
    for (int h = 0; h < 2; h++) {
        const float4 a = *(const float4*)(p00 + h*4);
        const float4 c2 = *(const float4*)(p01 + h*4);
        const float4 d = *(const float4*)(p10 + h*4);
        const float4 e = *(const float4*)(p11 + h*4);
        float4 s;
        s.x = f2tff(w00*a.x + w01*c2.x + w10*d.x + w11*e.x);
        s.y = f2tff(w00*a.y + w01*c2.y + w10*d.y + w11*e.y);
        s.z = f2tff(w00*a.z + w01*c2.z + w10*d.z + w11*e.z);
        s.w = f2tff(w00*a.w + w01*c2.w + w10*d.w + w11*e.w);
        *(float4*)(cp + h*4) = s;
    }
}

// ---------------- final: relu( bn2(d2) + bn3(res) ), float4 ------------------------
__global__ __launch_bounds__(256) void final_fuse(
    const float* __restrict__ d2, const float* __restrict__ res,
    const float* __restrict__ st,
    const float* __restrict__ g2, const float* __restrict__ bt2,
    const float* __restrict__ g3, const float* __restrict__ bt3,
    float* __restrict__ out)
{
    const int i4 = blockIdx.x*256 + threadIdx.x;     // float4 index
    const int c = (i4 >> 10) & 255;
    const float a2 = st[768 + c]  * g2[c];
    const float a3 = st[1280 + c] * g3[c];
    const float k2 = bt2[c] - st[512 + c]  * a2;
    const float k3 = bt3[c] - st[1024 + c] * a3;
    const float4 dv = *(const float4*)(d2  + (size_t)i4*4);
    const float4 rv = *(const float4*)(res + (size_t)i4*4);
    float4 o;
    o.x = fmaxf(dv.x*a2 + k2 + rv.x*a3 + k3, 0.f);
    o.y = fmaxf(dv.y*a2 + k2 + rv.y*a3 + k3, 0.f);
    o.z = fmaxf(dv.z*a2 + k2 + rv.z*a3 + k3, 0.f);
    o.w = fmaxf(dv.w*a2 + k2 + rv.w*a3 + k3, 0.f);
    *(float4*)(out + (size_t)i4*4) = o;
}

// ---------------- launcher -----------------------------------------------------------
extern "C" void kernel_launch(void* const* d_in, const int* in_sizes, int n_in,
                              void* d_out, int out_size)
{
    const float* x     = (const float*)d_in[0];
    const float* w1    = (const float*)d_in[2];
    const float* b1    = (const float*)d_in[3];
    const float* g1    = (const float*)d_in[4];
    const float* bt1   = (const float*)d_in[5];
    const float* w_off = (const float*)d_in[6];
    const float* b_off = (const float*)d_in[7];
    const float* w_mod = (const float*)d_in[8];
    const float* b_mod = (const float*)d_in[9];
    const float* w_d   = (const float*)d_in[10];
    const float* b_d   = (const float*)d_in[11];
    const float* g2    = (const float*)d_in[12];
    const float* bt2   = (const float*)d_in[13];
    const float* w_ds  = (const float*)d_in[14];
    const float* b_ds  = (const float*)d_in[15];
    const float* g3    = (const float*)d_in[16];
    const float* bt3   = (const float*)d_in[17];

    float *xt, *y1h, *d2, *res, *off, *msk, *col, *st, *ps, *pq;
    float *w1p, *wdp, *wop, *wds, *bp;
    cudaGetSymbolAddress((void**)&xt,  g_xt);
    cudaGetSymbolAddress((void**)&y1h, g_y1h);
    cudaGetSymbolAddress((void**)&d2,  g_d2);
    cudaGetSymbolAddress((void**)&res, g_res);
    cudaGetSymbolAddress((void**)&off, g_off);
    cudaGetSymbolAddress((void**)&msk, g_mask);
    cudaGetSymbolAddress((void**)&col, g_col);
    cudaGetSymbolAddress((void**)&st,  g_stats);
    cudaGetSymbolAddress((void**)&ps,  g_ps);
    cudaGetSymbolAddress((void**)&pq,  g_pq);
    cudaGetSymbolAddress((void**)&w1p, g_w1p);
    cudaGetSymbolAddress((void**)&wdp, g_wdp);
    cudaGetSymbolAddress((void**)&wop, g_wop);
    cudaGetSymbolAddress((void**)&wds, g_wds);
    cudaGetSymbolAddress((void**)&bp,  g_bp);

    const int SM128 = 3 * (128*36 + 128*36) * 4;   // 110592
    const int SM32  = 3 * (32*36  + 128*36) * 4;   // 69120
    cudaFuncSetAttribute(gemm_conv1,  cudaFuncAttributeMaxDynamicSharedMemorySize, SM128);
    cudaFuncSetAttribute(gemm_dual,   cudaFuncAttributeMaxDynamicSharedMemorySize, SM128);
    cudaFuncSetAttribute(gemm_offmod, cudaFuncAttributeMaxDynamicSharedMemorySize, SM32);

    // 0) merged prep: NHWC x, all weight permutes/rounds
    prep_all<<<13344, 256>>>(x, xt, w1, w1p, w_d, wdp,
                             w_off, w_mod, b_off, b_mod, wop, bp, w_ds, wds);
    // 1) conv1: implicit 3x3 GEMM -> y1h NHWC raw + fused stats partials
    gemm_conv1<<<dim3(32, 2, BN), 128, SM128>>>(w1p, xt, b1, y1h, ps, pq);
    bn_combine<<<1, 256>>>(ps, pq, st);
    // 2) BN1 + ReLU + round, in place (float4)
    bn_relu_nhwc<<<(int)((size_t)BN*HWn*C/1024), 256>>>(y1h, st, g1, bt1);
    // 3) offsets + modulation
    gemm_offmod<<<dim3(32, 1, BN), 128, SM32>>>(wop, y1h, bp, off, msk);
    // 4) bilinear gather -> col [b][pix][k]  (288 threads, zero smem)
    deform_sample<<<dim3(HWn, BN), 288>>>(y1h, off, msk, col);
    // 5) deform GEMM + 1x1 shortcut, grid-merged (R12 grid form)
    gemm_dual<<<dim3(32, 4, BN), 128, SM128>>>(
        wdp, col, b_d, d2, ps + 65536, pq + 65536,
        wds, xt,  b_ds, res, ps + 2*65536, pq + 2*65536);
    bn_combine_pair<<<2, 256>>>(ps, pq, st);
    // 6) fused BN2 + BN3 + add + ReLU (vectorized)
    final_fuse<<<BN*C*HWn/1024, 256>>>(d2, res, st, g2, bt2, g3, bt3, (float*)d_out);
}

// round 16
// speedup vs baseline: 1.3197x; 1.0365x over previous
#include <cuda_runtime.h>
#include <math.h>
#include <stdint.h>

#define BN 8
#define C 256
#define HWn 4096
#define KFULL 2304

// ---------------- scratch (device globals: allocation-free) ----------------
__device__ float g_xt [(size_t)BN*HWn*C];        // x NHWC, tf32-rounded
__device__ float g_y1h[(size_t)BN*HWn*C];        // conv1 NHWC raw -> (in place) bn+relu rounded
__device__ float g_d2 [(size_t)BN*C*HWn];        // deform conv raw NCHW
__device__ float g_res[(size_t)BN*C*HWn];        // 1x1 raw NCHW
__device__ float g_off[BN*18*HWn];
__device__ float g_mask[BN*9*HWn];
__device__ float g_col[(size_t)BN*HWn*KFULL];    // [b][pix][k=p*256+ci], rounded
__device__ float g_stats[6*256];
__device__ float g_ps[3*256*256];                // [cta][c]
__device__ float g_pq[3*256*256];
__device__ float g_w1p[256*KFULL];               // w1  -> [co][cb*288 + t*32 + ci_in]
__device__ float g_wdp[256*KFULL];               // w_d -> [co][t*256+ci] (col order)
__device__ float g_wop[32*KFULL];                // off+mod, halo K order
__device__ float g_wds[256*256];
__device__ float g_bp[32];

// ---------------- helpers -----------------------------------------------------
__device__ __forceinline__ unsigned f2tf(float v) {
    unsigned u; asm("cvt.rna.tf32.f32 %0, %1;" : "=r"(u) : "f"(v)); return u;
}
__device__ __forceinline__ float f2tff(float v) { return __uint_as_float(f2tf(v)); }
__device__ __forceinline__ uint32_t s2u(const void* p) {
    uint32_t a;
    asm("{ .reg .u64 t; cvta.to.shared.u64 t, %1; cvt.u32.u64 %0, t; }" : "=r"(a) : "l"(p));
    return a;
}
__device__ __forceinline__ void cpa16(uint32_t dst, const void* src, bool v) {
    int sz = v ? 16 : 0;
    asm volatile("cp.async.cg.shared.global [%0], [%1], 16, %2;"
                 :: "r"(dst), "l"(src), "r"(sz) : "memory");
}
__device__ __forceinline__ void mma8(float* d, const uint4& a, const uint2& b) {
    asm volatile("mma.sync.aligned.m16n8k8.row.col.f32.tf32.tf32.f32 "
        "{%0,%1,%2,%3}, {%4,%5,%6,%7}, {%8,%9}, {%0,%1,%2,%3};"
        : "+f"(d[0]), "+f"(d[1]), "+f"(d[2]), "+f"(d[3])
        : "r"(a.x), "r"(a.y), "r"(a.z), "r"(a.w), "r"(b.x), "r"(b.y));
}

// =================== halo-staged implicit 3x3 conv GEMM ==========================
// K order: k = ci_blk*288 + t*32 + ci_in. 9 consecutive chunks share one halo
// (4 rows x 66 cols x 32 ch, pixel pitch 36). A: 2-stage; halo: 2-buffer,
// staged one chunk ahead. wait_group(0); sync; stage(next); commit; compute.
// EPI 1: NHWC out (+bias) [+stats].  EPI 2: offsets/mask.
template<int M, int EPI, bool STATS>
__device__ __forceinline__ void conv_core(
    const float* __restrict__ A, const float* __restrict__ Bm,
    const float* __restrict__ bias,
    float* __restrict__ out0, float* __restrict__ out1,
    float* __restrict__ ps, float* __restrict__ pq,
    int pix0, int co0, int b, int cta, float* sm)
{
    constexpr int WMn = (M == 128) ? 2 : 1;
    constexpr int WNn = 4 / WMn;
    constexpr int MI  = M / (16 * WMn);
    constexpr int NT  = 128 / (8 * WNn);
    constexpr int APITCH = 36;
    constexpr int ABUF = M * APITCH;          // floats per A stage
    constexpr int HBUF = 4 * 66 * 36;         // 9504 floats per halo buffer

    const int tid = threadIdx.x, lane = tid & 31, warp = tid >> 5;
    const int wm = warp / WNn, wn = warp % WNn;
    const int g = lane >> 2, tig = lane & 3;
    const uint32_t smu = s2u(sm);
    const int r0 = pix0 >> 6;                 // first image row of this 128-pix tile

    float acc[MI][NT][4] = {};

    auto stageA = [&](int ic) {
        if (ic < 72) {
            const int k0 = ic << 5;
            uint32_t sA = smu + (ic & 1) * ABUF * 4;
            #pragma unroll
            for (int i = 0; i < M/16; i++) {
                int idx = tid + i*128;
                int row = idx >> 3, kq = idx & 7;
                cpa16(sA + (row*APITCH + kq*4)*4,
                      A + (size_t)(co0+row)*KFULL + k0 + kq*4, true);
            }
        }
    };
    auto stageHalo = [&](int cb) {
        if (cb < 8) {
            uint32_t sH = smu + 2*ABUF*4 + (cb & 1) * HBUF * 4;
            const float* src = Bm + (size_t)b*4096*256 + cb*32;
            for (int i = tid; i < 4*66*8; i += 128) {
                int hr = i / 528;             // 66*8
                int r = i - hr*528;
                int hc = r >> 3, c4 = r & 7;
                int grow = r0 - 1 + hr, gcol = hc - 1;
                bool v = (grow >= 0) && (grow < 64) && (gcol >= 0) && (gcol < 64);
                cpa16(sH + ((hr*66 + hc)*36 + c4*4)*4,
                      src + (size_t)(v ? (grow*64 + gcol) : 0)*256 + c4*4, v);
            }
        }
    };

    stageA(0);
    stageHalo(0);
    asm volatile("cp.async.commit_group;" ::: "memory");
    for (int ic = 0; ic < 72; ic++) {
        asm volatile("cp.async.wait_group 0;" ::: "memory");
        __syncthreads();
        stageA(ic + 1);
        if (((ic + 1) % 9) == 0) stageHalo((ic + 1) / 9);
        asm volatile("cp.async.commit_group;" ::: "memory");

        const int cb = ic / 9, t = ic - cb*9;
        const float* sA = sm + (ic & 1)*ABUF;
        const float* sH = sm + 2*ABUF + (cb & 1)*HBUF;
        const int lrow = (M == 128) ? wn : (wn >> 1);
        const int lcb  = (M == 128) ? 0  : (wn & 1)*32;
        // halo base for this warp/tap: ((lrow + t/3)*66 + t%3)*36
        const float* hbase = sH + ((lrow + t/3)*66 + (t - (t/3)*3))*36;

        #pragma unroll
        for (int k8 = 0; k8 < 4; k8++) {
            const int kb = k8 * 8;
            uint4 af[MI];
            #pragma unroll
            for (int mi = 0; mi < MI; mi++) {
                const int cw = wm*(MI*16) + mi*16;
                af[mi].x = __float_as_uint(sA[(cw+g  )*APITCH + kb+tig  ]);
                af[mi].y = __float_as_uint(sA[(cw+g+8)*APITCH + kb+tig  ]);
                af[mi].z = __float_as_uint(sA[(cw+g  )*APITCH + kb+tig+4]);
                af[mi].w = __float_as_uint(sA[(cw+g+8)*APITCH + kb+tig+4]);
            }
            #pragma unroll
            for (int nn = 0; nn < NT; nn++) {
                const int lcol = lcb + nn*8 + g;
                uint2 bb;
                bb.x = __float_as_uint(hbase[lcol*36 + kb+tig  ]);
                bb.y = __float_as_uint(hbase[lcol*36 + kb+tig+4]);
                #pragma unroll
                for (int mi = 0; mi < MI; mi++)
                    mma8(acc[mi][nn], af[mi], bb);
            }
        }
    }
    __syncthreads();

    // ---- epilogue (reuses smem) ----
    float* sE = sm;
    if (EPI == 1) {                      // NHWC out; 2 passes over 64-pix halves
        float sc = 0.f, sc2 = 0.f;
        #pragma unroll
        for (int pass = 0; pass < 2; pass++) {
            if (wn == pass) {
                #pragma unroll
                for (int mi = 0; mi < MI; mi++) {
                    const int r0e = wm*(MI*16) + mi*16 + g;
                    const float b0 = bias[co0 + r0e], b1 = bias[co0 + r0e + 8];
                    #pragma unroll
                    for (int nn = 0; nn < NT; nn++) {
                        const int pl = nn*8 + tig*2;
                        sE[pl*132 + r0e]       = acc[mi][nn][0] + b0;
                        sE[(pl+1)*132 + r0e]   = acc[mi][nn][1] + b0;
                        sE[pl*132 + r0e+8]     = acc[mi][nn][2] + b1;
                        sE[(pl+1)*132 + r0e+8] = acc[mi][nn][3] + b1;
                    }
                }
            }
            __syncthreads();
            #pragma unroll
            for (int i = 0; i < 16; i++) {
                int idx = tid + i*128;
                int pp = idx >> 5, c4 = idx & 31;
                float4 v = *(float4*)&sE[pp*132 + c4*4];
                *(float4*)(out0 + ((size_t)b*4096 + pix0 + pass*64 + pp)*256
                           + co0 + c4*4) = v;
            }
            if (STATS) {
                #pragma unroll 8
                for (int pp = 0; pp < 64; pp++) {
                    float v = sE[pp*132 + tid];
                    sc += v; sc2 += v*v;
                }
            }
            __syncthreads();
        }
        if (STATS) {
            ps[cta*256 + co0 + tid] = sc;
            pq[cta*256 + co0 + tid] = sc2;
        }
    } else {                             // EPI 2: offsets + mask (M=32)
        #pragma unroll
        for (int mi = 0; mi < MI; mi++)
            #pragma unroll
            for (int nn = 0; nn < NT; nn++) {
                const int r = mi*16 + g;
                const int pl = wn*(NT*8) + nn*8 + tig*2;
                sE[r*132 + pl]       = acc[mi][nn][0];
                sE[r*132 + pl+1]     = acc[mi][nn][1];
                sE[(r+8)*132 + pl]   = acc[mi][nn][2];
                sE[(r+8)*132 + pl+1] = acc[mi][nn][3];
            }
        __syncthreads();
        {
            const int pix = pix0 + tid;
            #pragma unroll
            for (int r = 0; r < 27; r++) {
                float v = sE[r*132 + tid] + bias[r];
                if (r < 18) out0[((size_t)b*18 + r)*4096 + pix] = v;
                else        out1[((size_t)b*9 + r - 18)*4096 + pix] = 2.f/(1.f + expf(-v));
            }
        }
    }
}

// =================== flat-B GEMM core (BMODE 0), unchanged from R15 =============
template<int M>
__device__ __forceinline__ void gemm_core0(
    const float* __restrict__ A, const float* __restrict__ Bm,
    const float* __restrict__ bias,
    float* __restrict__ out0,
    float* __restrict__ ps, float* __restrict__ pq,
    int Kdim, int ROWLEN, int pix0, int co0, int b, int cta, float* sm)
{
    constexpr int MI = 4, NT = 8;        // M=128, 2x2 warps
    constexpr int APITCH = 36;
    constexpr int ABUF = M * APITCH;
    constexpr int BBUF = 128 * APITCH;
    constexpr int STAGE = ABUF + BBUF;

    const int tid = threadIdx.x, lane = tid & 31, warp = tid >> 5;
    const int wm = warp >> 1, wn = warp & 1;
    const int g = lane >> 2, tig = lane & 3;
    const uint32_t smu = s2u(sm);

    float acc[MI][NT][4] = {};
    const int nch = Kdim >> 5;

    auto stage = [&](int ic) {
        if (ic < nch) {
            const int buf = ic % 3;
            const int k0 = ic << 5;
            uint32_t sA = smu + buf * STAGE * 4;
            uint32_t sB = sA + ABUF * 4;
            #pragma unroll
            for (int i = 0; i < M/16; i++) {
                int idx = tid + i*128;
                int row = idx >> 3, kq = idx & 7;
                cpa16(sA + (row*APITCH + kq*4)*4,
                      A + (size_t)(co0+row)*Kdim + k0 + kq*4, true);
            }
            #pragma unroll
            for (int i = 0; i < 8; i++) {
                int idx = tid + i*128;
                int pp = idx >> 3, kq = idx & 7;
                cpa16(sB + (pp*APITCH + kq*4)*4,
                      Bm + ((size_t)b*4096 + pix0 + pp)*(size_t)ROWLEN + k0 + kq*4, true);
            }
        }
        asm volatile("cp.async.commit_group;" ::: "memory");
    };

    stage(0);
    stage(1);
    for (int ic = 0; ic < nch; ic++) {
        const int buf = ic % 3;
        asm volatile("cp.async.wait_group 1;" ::: "memory");
        __syncthreads();
        stage(ic + 2);
        const float* sA = sm + buf*STAGE;
        const float* sB = sA + ABUF;
        #pragma unroll
        for (int k8 = 0; k8 < 4; k8++) {
            const int kb = k8 * 8;
            uint4 af[MI];
            #pragma unroll
            for (int mi = 0; mi < MI; mi++) {
                const int cw = wm*64 + mi*16;
                af[mi].x = __float_as_uint(sA[(cw+g  )*APITCH + kb+tig  ]);
                af[mi].y = __float_as_uint(sA[(cw+g+8)*APITCH + kb+tig  ]);
                af[mi].z = __float_as_uint(sA[(cw+g  )*APITCH + kb+tig+4]);
                af[mi].w = __float_as_uint(sA[(cw+g+8)*APITCH + kb+tig+4]);
            }
            #pragma unroll
            for (int nn = 0; nn < NT; nn++) {
                const int pc = wn*64 + nn*8 + g;
                uint2 bb;
                bb.x = __float_as_uint(sB[pc*APITCH + kb+tig  ]);
                bb.y = __float_as_uint(sB[pc*APITCH + kb+tig+4]);
                #pragma unroll
                for (int mi = 0; mi < MI; mi++)
                    mma8(acc[mi][nn], af[mi], bb);
            }
        }
    }
    __syncthreads();

    // NCHW epilogue + stats
    float* sE = sm;
    #pragma unroll
    for (int p = 0; p < 4; p++) {
        if (wm == (p >> 1)) {
            #pragma unroll
            for (int ml = 0; ml < 2; ml++) {
                const int mi = (p & 1)*2 + ml;
                const int r = ml*16 + g;
                const float b0 = bias[co0 + p*32 + r];
                const float b1 = bias[co0 + p*32 + r + 8];
                #pragma unroll
                for (int nn = 0; nn < NT; nn++) {
                    const int pl = wn*64 + nn*8 + tig*2;
                    sE[r*132 + pl]       = acc[mi][nn][0] + b0;
                    sE[r*132 + pl+1]     = acc[mi][nn][1] + b0;
                    sE[(r+8)*132 + pl]   = acc[mi][nn][2] + b1;
                    sE[(r+8)*132 + pl+1] = acc[mi][nn][3] + b1;
                }
            }
        }
        __syncthreads();
        #pragma unroll
        for (int i = 0; i < 8; i++) {
            int idx = tid + i*128;
            int r = idx >> 5, p4 = idx & 31;
            float4 v = *(float4*)&sE[r*132 + p4*4];
            *(float4*)(out0 + (((size_t)b*256 + co0 + p*32 + r) << 12)
                       + pix0 + p4*4) = v;
            float s  = v.x + v.y + v.z + v.w;
            float s2 = v.x*v.x + v.y*v.y + v.z*v.z + v.w*v.w;
            #pragma unroll
            for (int o = 16; o > 0; o >>= 1) {
                s  += __shfl_xor_sync(0xffffffffu, s,  o);
                s2 += __shfl_xor_sync(0xffffffffu, s2, o);
            }
            if (lane == 0) {
                ps[cta*256 + co0 + p*32 + r] = s;
                pq[cta*256 + co0 + p*32 + r] = s2;
            }
        }
        __syncthreads();
    }
}

// ---------------- kernel wrappers ------------------------------------------------
__global__ void __launch_bounds__(128, 2) gemm_conv1(
    const float* __restrict__ A, const float* __restrict__ Bm,
    const float* __restrict__ bias, float* __restrict__ out0,
    float* __restrict__ ps, float* __restrict__ pq)
{
    extern __shared__ float sm[];
    conv_core<128,1,true>(A, Bm, bias, out0, nullptr, ps, pq,
        blockIdx.x*128, blockIdx.y*128, blockIdx.z,
        blockIdx.x + (blockIdx.z << 5), sm);
}

__global__ void __launch_bounds__(128, 2) gemm_offmod(
    const float* __restrict__ A, const float* __restrict__ Bm,
    const float* __restrict__ bias,
    float* __restrict__ off, float* __restrict__ msk)
{
    extern __shared__ float sm[];
    conv_core<32,2,false>(A, Bm, bias, off, msk, nullptr, nullptr,
        blockIdx.x*128, 0, blockIdx.z, 0, sm);
}

// y<2: deform GEMM (K=2304, B=col).  y>=2: 1x1 shortcut (K=256, B=xt).
__global__ void __launch_bounds__(128, 2) gemm_dual(
    const float* __restrict__ wdp, const float* __restrict__ col,
    const float* __restrict__ b_d, float* __restrict__ d2,
    float* __restrict__ ps1, float* __restrict__ pq1,
    const float* __restrict__ wds, const float* __restrict__ xt,
    const float* __restrict__ b_ds, float* __restrict__ res,
    float* __restrict__ ps2, float* __restrict__ pq2)
{
    extern __shared__ float sm[];
    const int pix0 = blockIdx.x*128, b = blockIdx.z;
    const int cta = blockIdx.x + (blockIdx.z << 5);
    if (blockIdx.y < 2)
        gemm_core0<128>(wdp, col, b_d, d2, ps1, pq1,
            KFULL, KFULL, pix0, blockIdx.y*128, b, cta, sm);
    else
        gemm_core0<128>(wds, xt, b_ds, res, ps2, pq2,
            256, 256, pix0, (blockIdx.y-2)*128, b, cta, sm);
}

// ---------------- stats combine -------------------------------------------------
__global__ __launch_bounds__(256) void bn_combine(const float* __restrict__ ps,
    const float* __restrict__ pq, float* __restrict__ st)
{
    const int c = threadIdx.x;
    float s = 0.f, s2 = 0.f;
    #pragma unroll 8
    for (int j = 0; j < 256; j++) { s += ps[j*256 + c]; s2 += pq[j*256 + c]; }
    const float m = s * (1.f/32768.f);
    const float var = s2 * (1.f/32768.f) - m*m;
    st[c] = m;
    st[256 + c] = rsqrtf(var + 1e-5f);
}

__global__ __launch_bounds__(256) void bn_combine_pair(const float* __restrict__ ps,
    const float* __restrict__ pq, float* __restrict__ st)
{
    const int sel = blockIdx.x;
    const float* p = ps + (sel+1)*65536;
    const float* q = pq + (sel+1)*65536;
    const int c = threadIdx.x;
    float s = 0.f, s2 = 0.f;
    #pragma unroll 8
    for (int j = 0; j < 256; j++) { s += p[j*256 + c]; s2 += q[j*256 + c]; }
    const float m = s * (1.f/32768.f);
    const float var = s2 * (1.f/32768.f) - m*m;
    st[512 + sel*512 + c] = m;
    st[768 + sel*512 + c] = rsqrtf(var + 1e-5f);
}

// ---------------- merged prep kernel ---------------------------------------------
__global__ __launch_bounds__(256) void prep_all(
    const float* __restrict__ x, float* __restrict__ xt,
    const float* __restrict__ w1, float* __restrict__ w1p,
    const float* __restrict__ w_d, float* __restrict__ wdp,
    const float* __restrict__ w_off, const float* __restrict__ w_mod,
    const float* __restrict__ b_off, const float* __restrict__ b_mod,
    float* __restrict__ wop, float* __restrict__ bp,
    const float* __restrict__ w_ds, float* __restrict__ wds)
{
    __shared__ float tb[32][33];
    const int bx = blockIdx.x;
    if (bx < 8192) {                                  // NCHW->NHWC round of x
        const int b = bx >> 10, cy = (bx >> 7) & 7, cx = bx & 127;
        const int pix0 = cx*32, c0 = cy*32;
        const int tx = threadIdx.x & 31, ty = threadIdx.x >> 5;
        #pragma unroll
        for (int i = 0; i < 4; i++)
            tb[ty + i*8][tx] = f2tff(x[((size_t)b*256 + c0 + ty + i*8)*4096 + pix0 + tx]);
        __syncthreads();
        #pragma unroll
        for (int i = 0; i < 4; i++)
            xt[((size_t)b*4096 + pix0 + ty + i*8)*256 + c0 + tx] = tb[tx][ty + i*8];
    } else if (bx < 8192 + 2304) {                    // permute w1 (halo K order)
        int i = (bx - 8192)*256 + threadIdx.x;
        int co = i / KFULL, r = i - co*KFULL;
        int cb = r / 288, r2 = r - cb*288;
        int t = r2 >> 5, ci_in = r2 & 31;
        w1p[i] = f2tff(w1[co*KFULL + (cb*32 + ci_in)*9 + t]);
    } else if (bx < 8192 + 4608) {                    // permute w_d (col K order)
        int i = (bx - 8192 - 2304)*256 + threadIdx.x;
        int co = i / KFULL, r = i - co*KFULL;
        int t = r >> 8, ci = r & 255;
        wdp[i] = f2tff(w_d[co*KFULL + ci*9 + t]);
    } else if (bx < 8192 + 4896) {                    // pack offmod (halo K order)
        int i = (bx - 8192 - 4608)*256 + threadIdx.x;
        if (i < 32*KFULL) {
            int o = i / KFULL, r = i - o*KFULL;
            int cb = r / 288, r2 = r - cb*288;
            int t = r2 >> 5, ci_in = r2 & 31;
            int kk = (cb*32 + ci_in)*9 + t;
            float v = 0.f;
            if (o < 18)      v = w_off[o*KFULL + kk];
            else if (o < 27) v = w_mod[(o-18)*KFULL + kk];
            wop[i] = f2tff(v);
        }
        if (i < 27) bp[i] = (i < 18) ? b_off[i] : b_mod[i-18];
    } else {                                          // round w_ds
        int i = (bx - 8192 - 4896)*256 + threadIdx.x;
        wds[i] = f2tff(w_ds[i]);
    }
}

// in-place BN + ReLU + tf32 round on NHWC, float4
__global__ __launch_bounds__(256) void bn_relu_nhwc(float* __restrict__ y,
    const float* __restrict__ st, const float* __restrict__ g, const float* __restrict__ bt)
{
    const int i4 = blockIdx.x*256 + threadIdx.x;
    const int c0 = (i4 & 63) * 4;
    const float4 mn = *(const float4*)(st + c0);
    const float4 rs = *(const float4*)(st + 256 + c0);
    const float4 gg = *(const float4*)(g + c0);
    const float4 bb = *(const float4*)(bt + c0);
    float4 v = *(float4*)(y + (size_t)i4*4);
    v.x = f2tff(fmaxf((v.x - mn.x)*rs.x*gg.x + bb.x, 0.f));
    v.y = f2tff(fmaxf((v.y - mn.y)*rs.y*gg.y + bb.y, 0.f));
    v.z = f2tff(fmaxf((v.z - mn.z)*rs.z*gg.z + bb.z, 0.f));
    v.w = f2tff(fmaxf((v.w - mn.w)*rs.w*gg.w + bb.w, 0.f));
    *(float4*)(y + (size_t)i4*4) = v;
}

// ---------------- deformable gather on NHWC -> col [b][pix][k] -------------------
__global__ __launch_bounds__(288) void deform_sample(
    const float* __restrict__ y1h, const float* __restrict__ off,
    const float* __restrict__ msk, float* __restrict__ col)
{
    const int p = threadIdx.x >> 5, lane = threadIdx.x & 31;
    const int pix = blockIdx.x, b = blockIdx.y;
    const int ho = pix >> 6, wo = pix & 63;

    const float dy = off[((size_t)b*18 + 2*p    )*4096 + pix];
    const float dx = off[((size_t)b*18 + 2*p + 1)*4096 + pix];
    const float m  = msk[((size_t)b*9 + p)*4096 + pix];
    const float py = (float)(ho - 1 + p/3) + dy;
    const float px = (float)(wo - 1 + p%3) + dx;

    const float y0f = floorf(py), x0f = floorf(px);
    const float ly = py - y0f, lx = px - x0f;
    const int y0 = (int)y0f, x0 = (int)x0f;
    const int y1 = y0 + 1,  x1 = x0 + 1;
    float w00 = (1.f-ly)*(1.f-lx), w01 = (1.f-ly)*lx, w10 = ly*(1.f-lx), w11 = ly*lx;
    const bool vy0 = (y0 >= 0) && (y0 < 64), vy1 = (y1 >= 0) && (y1 < 64);
    const bool vx0 = (x0 >= 0) && (x0 < 64), vx1 = (x1 >= 0) && (x1 < 64);
    if (!(vy0 && vx0)) w00 = 0.f;
    if (!(vy0 && vx1)) w01 = 0.f;
    if (!(vy1 && vx0)) w10 = 0.f;
    if (!(vy1 && vx1)) w11 = 0.f;
    const int yc0 = min(max(y0, 0), 63), yc1 = min(max(y1, 0), 63);
    const int xc0 = min(max(x0, 0), 63), xc1 = min(max(x1, 0), 63);
    w00 *= m; w01 *= m; w10 *= m; w11 *= m;

    const float* base = y1h + (size_t)b*4096*256;
    const float* p00 = base + (size_t)(yc0*64 + xc0)*256 + lane*8;
    const float* p01 = base + (size_t)(yc0*64 + xc1)*256 + lane*8;
    const float* p10 = base + (size_t)(yc1*64 + xc0)*256 + lane*8;
    const float* p11 = base + (size_t)(yc1*64 + xc1)*256 + lane*8;
    float* cp = col + ((size_t)b*4096 + pix)*KFULL + p*256 + lane*8;

    #pragma unroll
    for (int h = 0; h < 2; h++) {
        const float4 a = *(const float4*)(p00 + h*4);
        const float4 c2 = *(const float4*)(p01 + h*4);
        const float4 d = *(const float4*)(p10 + h*4);
        const float4 e = *(const float4*)(p11 + h*4);
        float4 s;
        s.x = f2tff(w00*a.x + w01*c2.x + w10*d.x + w11*e.x);
        s.y = f2tff(w00*a.y + w01*c2.y + w10*d.y + w11*e.y);
        s.z = f2tff(w00*a.z + w01*c2.z + w10*d.z + w11*e.z);
        s.w = f2tff(w00*a.w + w01*c2.w + w10*d.w + w11*e.w);
        *(float4*)(cp + h*4) = s;
    }
}

// ---------------- final: relu( bn2(d2) + bn3(res) ), float4 ------------------------
__global__ __launch_bounds__(256) void final_fuse(
    const float* __restrict__ d2, const float* __restrict__ res,
    const float* __restrict__ st,
    const float* __restrict__ g2, const float* __restrict__ bt2,
    const float* __restrict__ g3, const float* __restrict__ bt3,
    float* __restrict__ out)
{
    const int i4 = blockIdx.x*256 + threadIdx.x;
    const int c = (i4 >> 10) & 255;
    const float a2 = st[768 + c]  * g2[c];
    const float a3 = st[1280 + c] * g3[c];
    const float k2 = bt2[c] - st[512 + c]  * a2;
    const float k3 = bt3[c] - st[1024 + c] * a3;
    const float4 dv = *(const float4*)(d2  + (size_t)i4*4);
    const float4 rv = *(const float4*)(res + (size_t)i4*4);
    float4 o;
    o.x = fmaxf(dv.x*a2 + k2 + rv.x*a3 + k3, 0.f);
    o.y = fmaxf(dv.y*a2 + k2 + rv.y*a3 + k3, 0.f);
    o.z = fmaxf(dv.z*a2 + k2 + rv.z*a3 + k3, 0.f);
    o.w = fmaxf(dv.w*a2 + k2 + rv.w*a3 + k3, 0.f);
    *(float4*)(out + (size_t)i4*4) = o;
}

// ---------------- launcher -----------------------------------------------------------
extern "C" void kernel_launch(void* const* d_in, const int* in_sizes, int n_in,
                              void* d_out, int out_size)
{
    const float* x     = (const float*)d_in[0];
    const float* w1    = (const float*)d_in[2];
    const float* b1    = (const float*)d_in[3];
    const float* g1    = (const float*)d_in[4];
    const float* bt1   = (const float*)d_in[5];
    const float* w_off = (const float*)d_in[6];
    const float* b_off = (const float*)d_in[7];
    const float* w_mod = (const float*)d_in[8];
    const float* b_mod = (const float*)d_in[9];
    const float* w_d   = (const float*)d_in[10];
    const float* b_d   = (const float*)d_in[11];
    const float* g2    = (const float*)d_in[12];
    const float* bt2   = (const float*)d_in[13];
    const float* w_ds  = (const float*)d_in[14];
    const float* b_ds  = (const float*)d_in[15];
    const float* g3    = (const float*)d_in[16];
    const float* bt3   = (const float*)d_in[17];

    float *xt, *y1h, *d2, *res, *off, *msk, *col, *st, *ps, *pq;
    float *w1p, *wdp, *wop, *wds, *bp;
    cudaGetSymbolAddress((void**)&xt,  g_xt);
    cudaGetSymbolAddress((void**)&y1h, g_y1h);
    cudaGetSymbolAddress((void**)&d2,  g_d2);
    cudaGetSymbolAddress((void**)&res, g_res);
    cudaGetSymbolAddress((void**)&off, g_off);
    cudaGetSymbolAddress((void**)&msk, g_mask);
    cudaGetSymbolAddress((void**)&col, g_col);
    cudaGetSymbolAddress((void**)&st,  g_stats);
    cudaGetSymbolAddress((void**)&ps,  g_ps);
    cudaGetSymbolAddress((void**)&pq,  g_pq);
    cudaGetSymbolAddress((void**)&w1p, g_w1p);
    cudaGetSymbolAddress((void**)&wdp, g_wdp);
    cudaGetSymbolAddress((void**)&wop, g_wop);
    cudaGetSymbolAddress((void**)&wds, g_wds);
    cudaGetSymbolAddress((void**)&bp,  g_bp);

    const int SMC1  = (2*128*36 + 2*9504) * 4;       // 112896
    const int SMOF  = (2*32*36  + 2*9504) * 4;       // 85248
    const int SM128 = 3 * (128*36 + 128*36) * 4;     // 110592
    cudaFuncSetAttribute(gemm_conv1,  cudaFuncAttributeMaxDynamicSharedMemorySize, SMC1);
    cudaFuncSetAttribute(gemm_dual,   cudaFuncAttributeMaxDynamicSharedMemorySize, SM128);
    cudaFuncSetAttribute(gemm_offmod, cudaFuncAttributeMaxDynamicSharedMemorySize, SMOF);

    // 0) merged prep: NHWC x, all weight permutes/rounds
    prep_all<<<13344, 256>>>(x, xt, w1, w1p, w_d, wdp,
                             w_off, w_mod, b_off, b_mod, wop, bp, w_ds, wds);
    // 1) conv1: halo-staged implicit 3x3 GEMM -> y1h NHWC + stats partials
    gemm_conv1<<<dim3(32, 2, BN), 128, SMC1>>>(w1p, xt, b1, y1h, ps, pq);
    bn_combine<<<1, 256>>>(ps, pq, st);
    // 2) BN1 + ReLU + round, in place (float4)
    bn_relu_nhwc<<<(int)((size_t)BN*HWn*C/1024), 256>>>(y1h, st, g1, bt1);
    // 3) offsets + modulation (halo-staged)
    gemm_offmod<<<dim3(32, 1, BN), 128, SMOF>>>(wop, y1h, bp, off, msk);
    // 4) bilinear gather -> col [b][pix][k]
    deform_sample<<<dim3(HWn, BN), 288>>>(y1h, off, msk, col);
    // 5) deform GEMM + 1x1 shortcut, grid-merged (R12/R15 form)
    gemm_dual<<<dim3(32, 4, BN), 128, SM128>>>(
        wdp, col, b_d, d2, ps + 65536, pq + 65536,
        wds, xt,  b_ds, res, ps + 2*65536, pq + 2*65536);
    bn_combine_pair<<<2, 256>>>(ps, pq, st);
    // 6) fused BN2 + BN3 + add + ReLU (vectorized)
    final_fuse<<<BN*C*HWn/1024, 256>>>(d2, res, st, g2, bt2, g3, bt3, (float*)d_out);
}

// round 17
// speedup vs baseline: 1.3575x; 1.0287x over previous
#include <cuda_runtime.h>
#include <math.h>
#include <stdint.h>

#define BN 8
#define C 256
#define HWn 4096
#define KFULL 2304

// ---------------- scratch (device globals: allocation-free) ----------------
__device__ float g_xt [(size_t)BN*HWn*C];        // x NHWC, tf32-rounded
__device__ float g_y1h[(size_t)BN*HWn*C];        // conv1 NHWC raw -> (in place) bn+relu rounded
__device__ float g_d2 [(size_t)BN*C*HWn];        // deform conv raw NCHW
__device__ float g_res[(size_t)BN*C*HWn];        // 1x1 raw NCHW
__device__ float g_off[BN*18*HWn];
__device__ float g_mask[BN*9*HWn];
__device__ float g_col[(size_t)BN*HWn*KFULL];    // [b][pix][k=p*256+ci], rounded
__device__ float g_stats[6*256];
__device__ float g_ps[3*256*256];                // [cta][c]
__device__ float g_pq[3*256*256];
__device__ float g_w1p[256*KFULL];               // w1  -> [co][cb*288 + t*32 + ci_in]
__device__ float g_wdp[256*KFULL];               // w_d -> [co][t*256+ci] (col order)
__device__ float g_wop[32*KFULL];                // off+mod, halo K order
__device__ float g_wds[256*256];
__device__ float g_bp[32];

// ---------------- helpers -----------------------------------------------------
__device__ __forceinline__ unsigned f2tf(float v) {
    unsigned u; asm("cvt.rna.tf32.f32 %0, %1;" : "=r"(u) : "f"(v)); return u;
}
__device__ __forceinline__ float f2tff(float v) { return __uint_as_float(f2tf(v)); }
__device__ __forceinline__ uint32_t s2u(const void* p) {
    uint32_t a;
    asm("{ .reg .u64 t; cvta.to.shared.u64 t, %1; cvt.u32.u64 %0, t; }" : "=r"(a) : "l"(p));
    return a;
}
__device__ __forceinline__ void cpa16(uint32_t dst, const void* src, bool v) {
    int sz = v ? 16 : 0;
    asm volatile("cp.async.cg.shared.global [%0], [%1], 16, %2;"
                 :: "r"(dst), "l"(src), "r"(sz) : "memory");
}
__device__ __forceinline__ void mma8(float* d, const uint4& a, const uint2& b) {
    asm volatile("mma.sync.aligned.m16n8k8.row.col.f32.tf32.tf32.f32 "
        "{%0,%1,%2,%3}, {%4,%5,%6,%7}, {%8,%9}, {%0,%1,%2,%3};"
        : "+f"(d[0]), "+f"(d[1]), "+f"(d[2]), "+f"(d[3])
        : "r"(a.x), "r"(a.y), "r"(a.z), "r"(a.w), "r"(b.x), "r"(b.y));
}

// =================== conv1: 256-pix halo-staged implicit 3x3 GEMM ================
// 256 threads, 8 warps (2 co x 4 pix-rows); warp tile 64co x 64pix (= 1 image row).
// K order: k = ci_blk*288 + t*32 + ci_in. Halo: 6 rows x 66 cols x 32ch, 2 buffers.
__global__ void __launch_bounds__(256, 1) gemm_conv1(
    const float* __restrict__ A, const float* __restrict__ Bm,
    const float* __restrict__ bias, float* __restrict__ out0,
    float* __restrict__ ps, float* __restrict__ pq)
{
    constexpr int APITCH = 36;
    constexpr int ABUF = 128 * APITCH;        // 4608 floats per A stage
    constexpr int HBUF = 6 * 66 * 36;         // 14256 floats per halo buffer
    extern __shared__ float sm[];

    const int tid = threadIdx.x, lane = tid & 31, warp = tid >> 5;
    const int wm = warp >> 2, wn = warp & 3;
    const int g = lane >> 2, tig = lane & 3;
    const uint32_t smu = s2u(sm);
    const int pix0 = blockIdx.x * 256;
    const int co0  = blockIdx.y * 128;
    const int b    = blockIdx.z;
    const int cta  = blockIdx.x + (blockIdx.z << 4);   // [0,128)
    const int r0   = pix0 >> 6;

    float acc[4][8][4] = {};

    auto stageA = [&](int ic) {
        if (ic < 72) {
            const int k0 = ic << 5;
            uint32_t sA = smu + (ic & 1) * ABUF * 4;
            #pragma unroll
            for (int i = 0; i < 4; i++) {
                int idx = tid + i*256;
                int row = idx >> 3, kq = idx & 7;
                cpa16(sA + (row*APITCH + kq*4)*4,
                      A + (size_t)(co0+row)*KFULL + k0 + kq*4, true);
            }
        }
    };
    auto stageHalo = [&](int cb) {
        if (cb < 8) {
            uint32_t sH = smu + 2*ABUF*4 + (cb & 1) * HBUF * 4;
            const float* src = Bm + (size_t)b*4096*256 + cb*32;
            for (int i = tid; i < 6*66*8; i += 256) {
                int hr = i / 528;
                int r = i - hr*528;
                int hc = r >> 3, c4 = r & 7;
                int grow = r0 - 1 + hr, gcol = hc - 1;
                bool v = (grow >= 0) && (grow < 64) && (gcol >= 0) && (gcol < 64);
                cpa16(sH + ((hr*66 + hc)*36 + c4*4)*4,
                      src + (size_t)(v ? (grow*64 + gcol) : 0)*256 + c4*4, v);
            }
        }
    };

    stageA(0);
    stageHalo(0);
    asm volatile("cp.async.commit_group;" ::: "memory");
    for (int ic = 0; ic < 72; ic++) {
        asm volatile("cp.async.wait_group 0;" ::: "memory");
        __syncthreads();
        stageA(ic + 1);
        if (((ic + 1) % 9) == 0) stageHalo((ic + 1) / 9);
        asm volatile("cp.async.commit_group;" ::: "memory");

        const int cb = ic / 9, t = ic - cb*9;
        const float* sA = sm + (ic & 1)*ABUF;
        const float* sH = sm + 2*ABUF + (cb & 1)*HBUF;
        const float* hbase = sH + ((wn + t/3)*66 + (t - (t/3)*3))*36;

        #pragma unroll
        for (int k8 = 0; k8 < 4; k8++) {
            const int kb = k8 * 8;
            uint4 af[4];
            #pragma unroll
            for (int mi = 0; mi < 4; mi++) {
                const int cw = wm*64 + mi*16;
                af[mi].x = __float_as_uint(sA[(cw+g  )*APITCH + kb+tig  ]);
                af[mi].y = __float_as_uint(sA[(cw+g+8)*APITCH + kb+tig  ]);
                af[mi].z = __float_as_uint(sA[(cw+g  )*APITCH + kb+tig+4]);
                af[mi].w = __float_as_uint(sA[(cw+g+8)*APITCH + kb+tig+4]);
            }
            #pragma unroll
            for (int nn = 0; nn < 8; nn++) {
                const int lcol = nn*8 + g;
                uint2 bb;
                bb.x = __float_as_uint(hbase[lcol*36 + kb+tig  ]);
                bb.y = __float_as_uint(hbase[lcol*36 + kb+tig+4]);
                #pragma unroll
                for (int mi = 0; mi < 4; mi++)
                    mma8(acc[mi][nn], af[mi], bb);
            }
        }
    }
    __syncthreads();

    // ---- epilogue: NHWC out + stats; 4 passes over 64-pix rows ----
    float* sE = sm;
    float sc = 0.f, sc2 = 0.f;
    #pragma unroll
    for (int pass = 0; pass < 4; pass++) {
        if (wn == pass) {
            #pragma unroll
            for (int mi = 0; mi < 4; mi++) {
                const int r0e = wm*64 + mi*16 + g;
                const float b0 = bias[co0 + r0e], b1 = bias[co0 + r0e + 8];
                #pragma unroll
                for (int nn = 0; nn < 8; nn++) {
                    const int pl = nn*8 + tig*2;
                    sE[pl*132 + r0e]       = acc[mi][nn][0] + b0;
                    sE[(pl+1)*132 + r0e]   = acc[mi][nn][1] + b0;
                    sE[pl*132 + r0e+8]     = acc[mi][nn][2] + b1;
                    sE[(pl+1)*132 + r0e+8] = acc[mi][nn][3] + b1;
                }
            }
        }
        __syncthreads();
        #pragma unroll
        for (int i = 0; i < 8; i++) {
            int idx = tid + i*256;
            int pp = idx >> 5, c4 = idx & 31;
            float4 v = *(float4*)&sE[pp*132 + c4*4];
            *(float4*)(out0 + ((size_t)b*4096 + pix0 + pass*64 + pp)*256
                       + co0 + c4*4) = v;
        }
        if (tid < 128) {
            #pragma unroll 8
            for (int pp = 0; pp < 64; pp++) {
                float v = sE[pp*132 + tid];
                sc += v; sc2 += v*v;
            }
        }
        __syncthreads();
    }
    if (tid < 128) {
        ps[cta*256 + co0 + tid] = sc;
        pq[cta*256 + co0 + tid] = sc2;
    }
}

// =================== offmod: 128-pix halo conv (unchanged from R16) ==============
__global__ void __launch_bounds__(128, 2) gemm_offmod(
    const float* __restrict__ A, const float* __restrict__ Bm,
    const float* __restrict__ bias,
    float* __restrict__ off, float* __restrict__ msk)
{
    constexpr int M = 32;
    constexpr int APITCH = 36;
    constexpr int ABUF = M * APITCH;
    constexpr int HBUF = 4 * 66 * 36;
    extern __shared__ float sm[];

    const int tid = threadIdx.x, lane = tid & 31, warp = tid >> 5;
    const int wn = warp;                 // WMn=1, WNn=4
    const int g = lane >> 2, tig = lane & 3;
    const uint32_t smu = s2u(sm);
    const int pix0 = blockIdx.x * 128;
    const int b    = blockIdx.z;
    const int r0   = pix0 >> 6;

    float acc[2][4][4] = {};

    auto stageA = [&](int ic) {
        if (ic < 72) {
            const int k0 = ic << 5;
            uint32_t sA = smu + (ic & 1) * ABUF * 4;
            #pragma unroll
            for (int i = 0; i < 2; i++) {
                int idx = tid + i*128;
                int row = idx >> 3, kq = idx & 7;
                cpa16(sA + (row*APITCH + kq*4)*4,
                      A + (size_t)row*KFULL + k0 + kq*4, true);
            }
        }
    };
    auto stageHalo = [&](int cb) {
        if (cb < 8) {
            uint32_t sH = smu + 2*ABUF*4 + (cb & 1) * HBUF * 4;
            const float* src = Bm + (size_t)b*4096*256 + cb*32;
            for (int i = tid; i < 4*66*8; i += 128) {
                int hr = i / 528;
                int r = i - hr*528;
                int hc = r >> 3, c4 = r & 7;
                int grow = r0 - 1 + hr, gcol = hc - 1;
                bool v = (grow >= 0) && (grow < 64) && (gcol >= 0) && (gcol < 64);
                cpa16(sH + ((hr*66 + hc)*36 + c4*4)*4,
                      src + (size_t)(v ? (grow*64 + gcol) : 0)*256 + c4*4, v);
            }
        }
    };

    stageA(0);
    stageHalo(0);
    asm volatile("cp.async.commit_group;" ::: "memory");
    for (int ic = 0; ic < 72; ic++) {
        asm volatile("cp.async.wait_group 0;" ::: "memory");
        __syncthreads();
        stageA(ic + 1);
        if (((ic + 1) % 9) == 0) stageHalo((ic + 1) / 9);
        asm volatile("cp.async.commit_group;" ::: "memory");

        const int cb = ic / 9, t = ic - cb*9;
        const float* sA = sm + (ic & 1)*ABUF;
        const float* sH = sm + 2*ABUF + (cb & 1)*HBUF;
        const int lrow = wn >> 1, lcb = (wn & 1)*32;
        const float* hbase = sH + ((lrow + t/3)*66 + (t - (t/3)*3))*36;

        #pragma unroll
        for (int k8 = 0; k8 < 4; k8++) {
            const int kb = k8 * 8;
            uint4 af[2];
            #pragma unroll
            for (int mi = 0; mi < 2; mi++) {
                const int cw = mi*16;
                af[mi].x = __float_as_uint(sA[(cw+g  )*APITCH + kb+tig  ]);
                af[mi].y = __float_as_uint(sA[(cw+g+8)*APITCH + kb+tig  ]);
                af[mi].z = __float_as_uint(sA[(cw+g  )*APITCH + kb+tig+4]);
                af[mi].w = __float_as_uint(sA[(cw+g+8)*APITCH + kb+tig+4]);
            }
            #pragma unroll
            for (int nn = 0; nn < 4; nn++) {
                const int lcol = lcb + nn*8 + g;
                uint2 bb;
                bb.x = __float_as_uint(hbase[lcol*36 + kb+tig  ]);
                bb.y = __float_as_uint(hbase[lcol*36 + kb+tig+4]);
                #pragma unroll
                for (int mi = 0; mi < 2; mi++)
                    mma8(acc[mi][nn], af[mi], bb);
            }
        }
    }
    __syncthreads();

    float* sE = sm;
    #pragma unroll
    for (int mi = 0; mi < 2; mi++)
        #pragma unroll
        for (int nn = 0; nn < 4; nn++) {
            const int r = mi*16 + g;
            const int pl = wn*32 + nn*8 + tig*2;
            sE[r*132 + pl]       = acc[mi][nn][0];
            sE[r*132 + pl+1]     = acc[mi][nn][1];
            sE[(r+8)*132 + pl]   = acc[mi][nn][2];
            sE[(r+8)*132 + pl+1] = acc[mi][nn][3];
        }
    __syncthreads();
    {
        const int pix = pix0 + tid;
        #pragma unroll
        for (int r = 0; r < 27; r++) {
            float v = sE[r*132 + tid] + g_bp[r];
            if (r < 18) off[((size_t)b*18 + r)*4096 + pix] = v;
            else        msk[((size_t)b*9 + r - 18)*4096 + pix] = 2.f/(1.f + expf(-v));
        }
    }
    (void)bias;
}

// =================== flat-B GEMM core (unchanged) ================================
template<int M>
__device__ __forceinline__ void gemm_core0(
    const float* __restrict__ A, const float* __restrict__ Bm,
    const float* __restrict__ bias,
    float* __restrict__ out0,
    float* __restrict__ ps, float* __restrict__ pq,
    int Kdim, int ROWLEN, int pix0, int co0, int b, int cta, float* sm)
{
    constexpr int MI = 4, NT = 8;
    constexpr int APITCH = 36;
    constexpr int ABUF = M * APITCH;
    constexpr int BBUF = 128 * APITCH;
    constexpr int STAGE = ABUF + BBUF;

    const int tid = threadIdx.x, lane = tid & 31, warp = tid >> 5;
    const int wm = warp >> 1, wn = warp & 1;
    const int g = lane >> 2, tig = lane & 3;
    const uint32_t smu = s2u(sm);

    float acc[MI][NT][4] = {};
    const int nch = Kdim >> 5;

    auto stage = [&](int ic) {
        if (ic < nch) {
            const int buf = ic % 3;
            const int k0 = ic << 5;
            uint32_t sA = smu + buf * STAGE * 4;
            uint32_t sB = sA + ABUF * 4;
            #pragma unroll
            for (int i = 0; i < M/16; i++) {
                int idx = tid + i*128;
                int row = idx >> 3, kq = idx & 7;
                cpa16(sA + (row*APITCH + kq*4)*4,
                      A + (size_t)(co0+row)*Kdim + k0 + kq*4, true);
            }
            #pragma unroll
            for (int i = 0; i < 8; i++) {
                int idx = tid + i*128;
                int pp = idx >> 3, kq = idx & 7;
                cpa16(sB + (pp*APITCH + kq*4)*4,
                      Bm + ((size_t)b*4096 + pix0 + pp)*(size_t)ROWLEN + k0 + kq*4, true);
            }
        }
        asm volatile("cp.async.commit_group;" ::: "memory");
    };

    stage(0);
    stage(1);
    for (int ic = 0; ic < nch; ic++) {
        const int buf = ic % 3;
        asm volatile("cp.async.wait_group 1;" ::: "memory");
        __syncthreads();
        stage(ic + 2);
        const float* sA = sm + buf*STAGE;
        const float* sB = sA + ABUF;
        #pragma unroll
        for (int k8 = 0; k8 < 4; k8++) {
            const int kb = k8 * 8;
            uint4 af[MI];
            #pragma unroll
            for (int mi = 0; mi < MI; mi++) {
                const int cw = wm*64 + mi*16;
                af[mi].x = __float_as_uint(sA[(cw+g  )*APITCH + kb+tig  ]);
                af[mi].y = __float_as_uint(sA[(cw+g+8)*APITCH + kb+tig  ]);
                af[mi].z = __float_as_uint(sA[(cw+g  )*APITCH + kb+tig+4]);
                af[mi].w = __float_as_uint(sA[(cw+g+8)*APITCH + kb+tig+4]);
            }
            #pragma unroll
            for (int nn = 0; nn < NT; nn++) {
                const int pc = wn*64 + nn*8 + g;
                uint2 bb;
                bb.x = __float_as_uint(sB[pc*APITCH + kb+tig  ]);
                bb.y = __float_as_uint(sB[pc*APITCH + kb+tig+4]);
                #pragma unroll
                for (int mi = 0; mi < MI; mi++)
                    mma8(acc[mi][nn], af[mi], bb);
            }
        }
    }
    __syncthreads();

    float* sE = sm;
    #pragma unroll
    for (int p = 0; p < 4; p++) {
        if (wm == (p >> 1)) {
            #pragma unroll
            for (int ml = 0; ml < 2; ml++) {
                const int mi = (p & 1)*2 + ml;
                const int r = ml*16 + g;
                const float b0 = bias[co0 + p*32 + r];
                const float b1 = bias[co0 + p*32 + r + 8];
                #pragma unroll
                for (int nn = 0; nn < NT; nn++) {
                    const int pl = wn*64 + nn*8 + tig*2;
                    sE[r*132 + pl]       = acc[mi][nn][0] + b0;
                    sE[r*132 + pl+1]     = acc[mi][nn][1] + b0;
                    sE[(r+8)*132 + pl]   = acc[mi][nn][2] + b1;
                    sE[(r+8)*132 + pl+1] = acc[mi][nn][3] + b1;
                }
            }
        }
        __syncthreads();
        #pragma unroll
        for (int i = 0; i < 8; i++) {
            int idx = tid + i*128;
            int r = idx >> 5, p4 = idx & 31;
            float4 v = *(float4*)&sE[r*132 + p4*4];
            *(float4*)(out0 + (((size_t)b*256 + co0 + p*32 + r) << 12)
                       + pix0 + p4*4) = v;
            float s  = v.x + v.y + v.z + v.w;
            float s2 = v.x*v.x + v.y*v.y + v.z*v.z + v.w*v.w;
            #pragma unroll
            for (int o = 16; o > 0; o >>= 1) {
                s  += __shfl_xor_sync(0xffffffffu, s,  o);
                s2 += __shfl_xor_sync(0xffffffffu, s2, o);
            }
            if (lane == 0) {
                ps[cta*256 + co0 + p*32 + r] = s;
                pq[cta*256 + co0 + p*32 + r] = s2;
            }
        }
        __syncthreads();
    }
}

// y<2: deform GEMM (K=2304, B=col).  y>=2: 1x1 shortcut (K=256, B=xt).
__global__ void __launch_bounds__(128, 2) gemm_dual(
    const float* __restrict__ wdp, const float* __restrict__ col,
    const float* __restrict__ b_d, float* __restrict__ d2,
    float* __restrict__ ps1, float* __restrict__ pq1,
    const float* __restrict__ wds, const float* __restrict__ xt,
    const float* __restrict__ b_ds, float* __restrict__ res,
    float* __restrict__ ps2, float* __restrict__ pq2)
{
    extern __shared__ float sm[];
    const int pix0 = blockIdx.x*128, b = blockIdx.z;
    const int cta = blockIdx.x + (blockIdx.z << 5);
    if (blockIdx.y < 2)
        gemm_core0<128>(wdp, col, b_d, d2, ps1, pq1,
            KFULL, KFULL, pix0, blockIdx.y*128, b, cta, sm);
    else
        gemm_core0<128>(wds, xt, b_ds, res, ps2, pq2,
            256, 256, pix0, (blockIdx.y-2)*128, b, cta, sm);
}

// ---------------- stats combine (n partial rows) -----------------------------------
__global__ __launch_bounds__(256) void bn_combine(const float* __restrict__ ps,
    const float* __restrict__ pq, float* __restrict__ st, int n)
{
    const int c = threadIdx.x;
    float s = 0.f, s2 = 0.f;
    #pragma unroll 8
    for (int j = 0; j < n; j++) { s += ps[j*256 + c]; s2 += pq[j*256 + c]; }
    const float m = s * (1.f/32768.f);
    const float var = s2 * (1.f/32768.f) - m*m;
    st[c] = m;
    st[256 + c] = rsqrtf(var + 1e-5f);
}

__global__ __launch_bounds__(256) void bn_combine_pair(const float* __restrict__ ps,
    const float* __restrict__ pq, float* __restrict__ st)
{
    const int sel = blockIdx.x;
    const float* p = ps + (sel+1)*65536;
    const float* q = pq + (sel+1)*65536;
    const int c = threadIdx.x;
    float s = 0.f, s2 = 0.f;
    #pragma unroll 8
    for (int j = 0; j < 256; j++) { s += p[j*256 + c]; s2 += q[j*256 + c]; }
    const float m = s * (1.f/32768.f);
    const float var = s2 * (1.f/32768.f) - m*m;
    st[512 + sel*512 + c] = m;
    st[768 + sel*512 + c] = rsqrtf(var + 1e-5f);
}

// ---------------- merged prep kernel ---------------------------------------------
__global__ __launch_bounds__(256) void prep_all(
    const float* __restrict__ x, float* __restrict__ xt,
    const float* __restrict__ w1, float* __restrict__ w1p,
    const float* __restrict__ w_d, float* __restrict__ wdp,
    const float* __restrict__ w_off, const float* __restrict__ w_mod,
    const float* __restrict__ b_off, const float* __restrict__ b_mod,
    float* __restrict__ wop, float* __restrict__ bp,
    const float* __restrict__ w_ds, float* __restrict__ wds)
{
    __shared__ float tb[32][33];
    const int bx = blockIdx.x;
    if (bx < 8192) {
        const int b = bx >> 10, cy = (bx >> 7) & 7, cx = bx & 127;
        const int pix0 = cx*32, c0 = cy*32;
        const int tx = threadIdx.x & 31, ty = threadIdx.x >> 5;
        #pragma unroll
        for (int i = 0; i < 4; i++)
            tb[ty + i*8][tx] = f2tff(x[((size_t)b*256 + c0 + ty + i*8)*4096 + pix0 + tx]);
        __syncthreads();
        #pragma unroll
        for (int i = 0; i < 4; i++)
            xt[((size_t)b*4096 + pix0 + ty + i*8)*256 + c0 + tx] = tb[tx][ty + i*8];
    } else if (bx < 8192 + 2304) {
        int i = (bx - 8192)*256 + threadIdx.x;
        int co = i / KFULL, r = i - co*KFULL;
        int cb = r / 288, r2 = r - cb*288;
        int t = r2 >> 5, ci_in = r2 & 31;
        w1p[i] = f2tff(w1[co*KFULL + (cb*32 + ci_in)*9 + t]);
    } else if (bx < 8192 + 4608) {
        int i = (bx - 8192 - 2304)*256 + threadIdx.x;
        int co = i / KFULL, r = i - co*KFULL;
        int t = r >> 8, ci = r & 255;
        wdp[i] = f2tff(w_d[co*KFULL + ci*9 + t]);
    } else if (bx < 8192 + 4896) {
        int i = (bx - 8192 - 4608)*256 + threadIdx.x;
        if (i < 32*KFULL) {
            int o = i / KFULL, r = i - o*KFULL;
            int cb = r / 288, r2 = r - cb*288;
            int t = r2 >> 5, ci_in = r2 & 31;
            int kk = (cb*32 + ci_in)*9 + t;
            float v = 0.f;
            if (o < 18)      v = w_off[o*KFULL + kk];
            else if (o < 27) v = w_mod[(o-18)*KFULL + kk];
            wop[i] = f2tff(v);
        }
        if (i < 27) bp[i] = (i < 18) ? b_off[i] : b_mod[i-18];
    } else {
        int i = (bx - 8192 - 4896)*256 + threadIdx.x;
        wds[i] = f2tff(w_ds[i]);
    }
}

// in-place BN + ReLU + tf32 round on NHWC, float4
__global__ __launch_bounds__(256) void bn_relu_nhwc(float* __restrict__ y,
    const float* __restrict__ st, const float* __restrict__ g, const float* __restrict__ bt)
{
    const int i4 = blockIdx.x*256 + threadIdx.x;
    const int c0 = (i4 & 63) * 4;
    const float4 mn = *(const float4*)(st + c0);
    const float4 rs = *(const float4*)(st + 256 + c0);
    const float4 gg = *(const float4*)(g + c0);
    const float4 bb = *(const float4*)(bt + c0);
    float4 v = *(float4*)(y + (size_t)i4*4);
    v.x = f2tff(fmaxf((v.x - mn.x)*rs.x*gg.x + bb.x, 0.f));
    v.y = f2tff(fmaxf((v.y - mn.y)*rs.y*gg.y + bb.y, 0.f));
    v.z = f2tff(fmaxf((v.z - mn.z)*rs.z*gg.z + bb.z, 0.f));
    v.w = f2tff(fmaxf((v.w - mn.w)*rs.w*gg.w + bb.w, 0.f));
    *(float4*)(y + (size_t)i4*4) = v;
}

// ---------------- deformable gather on NHWC -> col [b][pix][k] -------------------
__global__ __launch_bounds__(288) void deform_sample(
    const float* __restrict__ y1h, const float* __restrict__ off,
    const float* __restrict__ msk, float* __restrict__ col)
{
    const int p = threadIdx.x >> 5, lane = threadIdx.x & 31;
    const int pix = blockIdx.x, b = blockIdx.y;
    const int ho = pix >> 6, wo = pix & 63;

    const float dy = off[((size_t)b*18 + 2*p    )*4096 + pix];
    const float dx = off[((size_t)b*18 + 2*p + 1)*4096 + pix];
    const float m  = msk[((size_t)b*9 + p)*4096 + pix];
    const float py = (float)(ho - 1 + p/3) + dy;
    const float px = (float)(wo - 1 + p%3) + dx;

    const float y0f = floorf(py), x0f = floorf(px);
    const float ly = py - y0f, lx = px - x0f;
    const int y0 = (int)y0f, x0 = (int)x0f;
    const int y1 = y0 + 1,  x1 = x0 + 1;
    float w00 = (1.f-ly)*(1.f-lx), w01 = (1.f-ly)*lx, w10 = ly*(1.f-lx), w11 = ly*lx;
    const bool vy0 = (y0 >= 0) && (y0 < 64), vy1 = (y1 >= 0) && (y1 < 64);
    const bool vx0 = (x0 >= 0) && (x0 < 64), vx1 = (x1 >= 0) && (x1 < 64);
    if (!(vy0 && vx0)) w00 = 0.f;
    if (!(vy0 && vx1)) w01 = 0.f;
    if (!(vy1 && vx0)) w10 = 0.f;
    if (!(vy1 && vx1)) w11 = 0.f;
    const int yc0 = min(max(y0, 0), 63), yc1 = min(max(y1, 0), 63);
    const int xc0 = min(max(x0, 0), 63), xc1 = min(max(x1, 0), 63);
    w00 *= m; w01 *= m; w10 *= m; w11 *= m;

    const float* base = y1h + (size_t)b*4096*256;
    const float* p00 = base + (size_t)(yc0*64 + xc0)*256 + lane*8;
    const float* p01 = base + (size_t)(yc0*64 + xc1)*256 + lane*8;
    const float* p10 = base + (size_t)(yc1*64 + xc0)*256 + lane*8;
    const float* p11 = base + (size_t)(yc1*64 + xc1)*256 + lane*8;
    float* cp = col + ((size_t)b*4096 + pix)*KFULL + p*256 + lane*8;

    #pragma unroll
    for (int h = 0; h < 2; h++) {
        const float4 a = *(const float4*)(p00 + h*4);
        const float4 c2 = *(const float4*)(p01 + h*4);
        const float4 d = *(const float4*)(p10 + h*4);
        const float4 e = *(const float4*)(p11 + h*4);
        float4 s;
        s.x = f2tff(w00*a.x + w01*c2.x + w10*d.x + w11*e.x);
        s.y = f2tff(w00*a.y + w01*c2.y + w10*d.y + w11*e.y);
        s.z = f2tff(w00*a.z + w01*c2.z + w10*d.z + w11*e.z);
        s.w = f2tff(w00*a.w + w01*c2.w + w10*d.w + w11*e.w);
        *(float4*)(cp + h*4) = s;
    }
}

// ---------------- final: relu( bn2(d2) + bn3(res) ), float4 ------------------------
__global__ __launch_bounds__(256) void final_fuse(
    const float* __restrict__ d2, const float* __restrict__ res,
    const float* __restrict__ st,
    const float* __restrict__ g2, const float* __restrict__ bt2,
    const float* __restrict__ g3, const float* __restrict__ bt3,
    float* __restrict__ out)
{
    const int i4 = blockIdx.x*256 + threadIdx.x;
    const int c = (i4 >> 10) & 255;
    const float a2 = st[768 + c]  * g2[c];
    const float a3 = st[1280 + c] * g3[c];
    const float k2 = bt2[c] - st[512 + c]  * a2;
    const float k3 = bt3[c] - st[1024 + c] * a3;
    const float4 dv = *(const float4*)(d2  + (size_t)i4*4);
    const float4 rv = *(const float4*)(res + (size_t)i4*4);
    float4 o;
    o.x = fmaxf(dv.x*a2 + k2 + rv.x*a3 + k3, 0.f);
    o.y = fmaxf(dv.y*a2 + k2 + rv.y*a3 + k3, 0.f);
    o.z = fmaxf(dv.z*a2 + k2 + rv.z*a3 + k3, 0.f);
    o.w = fmaxf(dv.w*a2 + k2 + rv.w*a3 + k3, 0.f);
    *(float4*)(out + (size_t)i4*4) = o;
}

// ---------------- launcher -----------------------------------------------------------
extern "C" void kernel_launch(void* const* d_in, const int* in_sizes, int n_in,
                              void* d_out, int out_size)
{
    const float* x     = (const float*)d_in[0];
    const float* w1    = (const float*)d_in[2];
    const float* b1    = (const float*)d_in[3];
    const float* g1    = (const float*)d_in[4];
    const float* bt1   = (const float*)d_in[5];
    const float* w_off = (const float*)d_in[6];
    const float* b_off = (const float*)d_in[7];
    const float* w_mod = (const float*)d_in[8];
    const float* b_mod = (const float*)d_in[9];
    const float* w_d   = (const float*)d_in[10];
    const float* b_d   = (const float*)d_in[11];
    const float* g2    = (const float*)d_in[12];
    const float* bt2   = (const float*)d_in[13];
    const float* w_ds  = (const float*)d_in[14];
    const float* b_ds  = (const float*)d_in[15];
    const float* g3    = (const float*)d_in[16];
    const float* bt3   = (const float*)d_in[17];

    float *xt, *y1h, *d2, *res, *off, *msk, *col, *st, *ps, *pq;
    float *w1p, *wdp, *wop, *wds, *bp;
    cudaGetSymbolAddress((void**)&xt,  g_xt);
    cudaGetSymbolAddress((void**)&y1h, g_y1h);
    cudaGetSymbolAddress((void**)&d2,  g_d2);
    cudaGetSymbolAddress((void**)&res, g_res);
    cudaGetSymbolAddress((void**)&off, g_off);
    cudaGetSymbolAddress((void**)&msk, g_mask);
    cudaGetSymbolAddress((void**)&col, g_col);
    cudaGetSymbolAddress((void**)&st,  g_stats);
    cudaGetSymbolAddress((void**)&ps,  g_ps);
    cudaGetSymbolAddress((void**)&pq,  g_pq);
    cudaGetSymbolAddress((void**)&w1p, g_w1p);
    cudaGetSymbolAddress((void**)&wdp, g_wdp);
    cudaGetSymbolAddress((void**)&wop, g_wop);
    cudaGetSymbolAddress((void**)&wds, g_wds);
    cudaGetSymbolAddress((void**)&bp,  g_bp);

    const int SMC1  = (2*128*36 + 2*6*66*36) * 4;    // 150912
    const int SMOF  = (2*32*36  + 2*4*66*36) * 4;    // 85248
    const int SM128 = 3 * (128*36 + 128*36) * 4;     // 110592
    cudaFuncSetAttribute(gemm_conv1,  cudaFuncAttributeMaxDynamicSharedMemorySize, SMC1);
    cudaFuncSetAttribute(gemm_dual,   cudaFuncAttributeMaxDynamicSharedMemorySize, SM128);
    cudaFuncSetAttribute(gemm_offmod, cudaFuncAttributeMaxDynamicSharedMemorySize, SMOF);

    // 0) merged prep: NHWC x, all weight permutes/rounds
    prep_all<<<13344, 256>>>(x, xt, w1, w1p, w_d, wdp,
                             w_off, w_mod, b_off, b_mod, wop, bp, w_ds, wds);
    // 1) conv1: 256-pix halo implicit GEMM -> y1h NHWC + stats partials (128 ctas)
    gemm_conv1<<<dim3(16, 2, BN), 256, SMC1>>>(w1p, xt, b1, y1h, ps, pq);
    bn_combine<<<1, 256>>>(ps, pq, st, 128);
    // 2) BN1 + ReLU + round, in place (float4)
    bn_relu_nhwc<<<(int)((size_t)BN*HWn*C/1024), 256>>>(y1h, st, g1, bt1);
    // 3) offsets + modulation (halo-staged)
    gemm_offmod<<<dim3(32, 1, BN), 128, SMOF>>>(wop, y1h, bp, off, msk);
    // 4) bilinear gather -> col [b][pix][k]
    deform_sample<<<dim3(HWn, BN), 288>>>(y1h, off, msk, col);
    // 5) deform GEMM + 1x1 shortcut, grid-merged
    gemm_dual<<<dim3(32, 4, BN), 128, SM128>>>(
        wdp, col, b_d, d2, ps + 65536, pq + 65536,
        wds, xt,  b_ds, res, ps + 2*65536, pq + 2*65536);
    bn_combine_pair<<<2, 256>>>(ps, pq, st);
    // 6) fused BN2 + BN3 + add + ReLU (vectorized)
    final_fuse<<<BN*C*HWn/1024, 256>>>(d2, res, st, g2, bt2, g3, bt3, (float*)d_out);
}